// round 1
// baseline (speedup 1.0000x reference)
#include <cuda_runtime.h>
#include <math.h>

// Problem constants
#define NB 4
#define NS 2048
#define ND 1024
#define NH 8
#define NK 128          // DEPTH (head dim)
#define NL 4
#define NM (NB*NS)      // 8192 rows

// ---------------- scratch (device globals; no allocation allowed) ----------
__device__ float g_x [NM*ND];
__device__ float g_q [NM*ND];   // [B,H,S,NK]
__device__ float g_k [NM*ND];
__device__ float g_v [NM*ND];
__device__ float g_ao[NM*ND];   // attention output, concat-head layout [B,S,D]
__device__ float g_t1[NM*ND];
__device__ float g_t2[NM*ND];

// ---------------- helpers ---------------------------------------------------
__device__ __forceinline__ float gelu_exact(float x) {
    return 0.5f * x * (1.0f + erff(x * 0.7071067811865476f));
}

// ---------------- copy ------------------------------------------------------
__global__ void copy_f4(const float4* __restrict__ s, float4* __restrict__ d) {
    int i = blockIdx.x * blockDim.x + threadIdx.x;
    d[i] = s[i];
}

// ---------------- generic GEMM: C = act(A[ M x1024 ] @ W[1024 x 1024] + b) --
__global__ __launch_bounds__(256) void gemm_kernel(
    const float* __restrict__ A, const float* __restrict__ W,
    const float* __restrict__ bias, float* __restrict__ C, int act)
{
    __shared__ float As[16][132];
    __shared__ float Bs[16][128];
    const int tid = threadIdx.x;
    const int tx = tid & 15, ty = tid >> 4;
    const int m0 = blockIdx.y * 128;
    const int n0 = blockIdx.x * 128;

    float acc[8][8];
#pragma unroll
    for (int i = 0; i < 8; i++)
#pragma unroll
        for (int j = 0; j < 8; j++) acc[i][j] = 0.f;

    const int ra = tid >> 2, ca = (tid & 3) * 4;   // A loader
    const int rb = tid >> 5, cb = (tid & 31) * 4;  // B loader

    for (int k0 = 0; k0 < ND; k0 += 16) {
#pragma unroll
        for (int u = 0; u < 2; u++) {
            int r = ra + u * 64;
            float4 v = *(const float4*)(A + (size_t)(m0 + r) * ND + k0 + ca);
            As[ca + 0][r] = v.x; As[ca + 1][r] = v.y;
            As[ca + 2][r] = v.z; As[ca + 3][r] = v.w;
        }
#pragma unroll
        for (int u = 0; u < 2; u++) {
            int kk = rb + u * 8;
            *(float4*)(&Bs[kk][cb]) =
                *(const float4*)(W + (size_t)(k0 + kk) * ND + n0 + cb);
        }
        __syncthreads();
#pragma unroll
        for (int kk = 0; kk < 16; kk++) {
            float a[8], b[8];
            *(float4*)(a)     = *(const float4*)(&As[kk][ty * 8]);
            *(float4*)(a + 4) = *(const float4*)(&As[kk][ty * 8 + 4]);
            *(float4*)(b)     = *(const float4*)(&Bs[kk][tx * 8]);
            *(float4*)(b + 4) = *(const float4*)(&Bs[kk][tx * 8 + 4]);
#pragma unroll
            for (int i = 0; i < 8; i++)
#pragma unroll
                for (int j = 0; j < 8; j++)
                    acc[i][j] = fmaf(a[i], b[j], acc[i][j]);
        }
        __syncthreads();
    }
#pragma unroll
    for (int i = 0; i < 8; i++) {
        int m = m0 + ty * 8 + i;
        float out[8];
#pragma unroll
        for (int j = 0; j < 8; j++) {
            float v = acc[i][j] + bias[n0 + tx * 8 + j];
            out[j] = act ? gelu_exact(v) : v;
        }
        *(float4*)(C + (size_t)m * ND + n0 + tx * 8)     = *(float4*)(out);
        *(float4*)(C + (size_t)m * ND + n0 + tx * 8 + 4) = *(float4*)(out + 4);
    }
}

// ---------------- QKV GEMM: per-head projection, scatter to [B,H,S,NK] ------
__global__ __launch_bounds__(256) void qkv_kernel(
    const float* __restrict__ X,
    const float* __restrict__ Wq, const float* __restrict__ Wk, const float* __restrict__ Wv,
    const float* __restrict__ Bq, const float* __restrict__ Bk, const float* __restrict__ Bv,
    float* __restrict__ Qo, float* __restrict__ Ko, float* __restrict__ Vo)
{
    const int h  = blockIdx.x;
    const int m0 = blockIdx.y * 128;
    const int w  = blockIdx.z;
    const float* W  = (w == 0) ? Wq : (w == 1) ? Wk : Wv;
    const float* Bi = (w == 0) ? Bq : (w == 1) ? Bk : Bv;
    float*       O  = (w == 0) ? Qo : (w == 1) ? Ko : Vo;
    W  += (size_t)h * ND * NK;
    Bi += h * NK;

    __shared__ float As[16][132];
    __shared__ float Bs[16][128];
    const int tid = threadIdx.x;
    const int tx = tid & 15, ty = tid >> 4;

    float acc[8][8];
#pragma unroll
    for (int i = 0; i < 8; i++)
#pragma unroll
        for (int j = 0; j < 8; j++) acc[i][j] = 0.f;

    const int ra = tid >> 2, ca = (tid & 3) * 4;
    const int rb = tid >> 5, cb = (tid & 31) * 4;

    for (int k0 = 0; k0 < ND; k0 += 16) {
#pragma unroll
        for (int u = 0; u < 2; u++) {
            int r = ra + u * 64;
            float4 v = *(const float4*)(X + (size_t)(m0 + r) * ND + k0 + ca);
            As[ca + 0][r] = v.x; As[ca + 1][r] = v.y;
            As[ca + 2][r] = v.z; As[ca + 3][r] = v.w;
        }
#pragma unroll
        for (int u = 0; u < 2; u++) {
            int kk = rb + u * 8;
            *(float4*)(&Bs[kk][cb]) =
                *(const float4*)(W + (size_t)(k0 + kk) * NK + cb);
        }
        __syncthreads();
#pragma unroll
        for (int kk = 0; kk < 16; kk++) {
            float a[8], b[8];
            *(float4*)(a)     = *(const float4*)(&As[kk][ty * 8]);
            *(float4*)(a + 4) = *(const float4*)(&As[kk][ty * 8 + 4]);
            *(float4*)(b)     = *(const float4*)(&Bs[kk][tx * 8]);
            *(float4*)(b + 4) = *(const float4*)(&Bs[kk][tx * 8 + 4]);
#pragma unroll
            for (int i = 0; i < 8; i++)
#pragma unroll
                for (int j = 0; j < 8; j++)
                    acc[i][j] = fmaf(a[i], b[j], acc[i][j]);
        }
        __syncthreads();
    }
#pragma unroll
    for (int i = 0; i < 8; i++) {
        int m = m0 + ty * 8 + i;
        int bb = m >> 11;           // S = 2048
        int s  = m & (NS - 1);
        float out[8];
#pragma unroll
        for (int j = 0; j < 8; j++) out[j] = acc[i][j] + Bi[tx * 8 + j];
        float* dst = O + ((size_t)(bb * NH + h) * NS + s) * NK + tx * 8;
        *(float4*)(dst)     = *(float4*)(out);
        *(float4*)(dst + 4) = *(float4*)(out + 4);
    }
}

// ---------------- flash attention (fp32, online softmax) --------------------
#define QSTR 65
#define PSTR 65
#define ATTN_SMEM_FLOATS (128*QSTR*2 + 64*128 + 64*PSTR + 192)
#define ATTN_SMEM_BYTES  (ATTN_SMEM_FLOATS * 4)

__global__ __launch_bounds__(256) void attn_kernel(
    const float* __restrict__ Qg, const float* __restrict__ Kg,
    const float* __restrict__ Vg, const int* __restrict__ Mg,
    float* __restrict__ Og)
{
    extern __shared__ float sm[];
    float* Qs  = sm;                         // [128][65], d-major
    float* Ks  = Qs + 128 * QSTR;            // [128][65], d-major
    float* Vs  = Ks + 128 * QSTR;            // [64][128], t-major
    float* Ps  = Vs + 64 * 128;              // [64][65]
    float* m_s = Ps + 64 * PSTR;
    float* l_s = m_s + 64;
    float* c_s = l_s + 64;

    const int tid = threadIdx.x;
    const int bh = blockIdx.y;
    const int b = bh >> 3, h = bh & 7;
    const int q0 = blockIdx.x * 64;

    // load Q tile [64 x 128], transposed into Qs[d][r]
    const float* Qb = Qg + ((size_t)bh * NS + q0) * NK;
#pragma unroll
    for (int it = 0; it < 8; it++) {
        int l = tid + it * 256;
        int r = l >> 5, c4 = (l & 31) * 4;
        float4 v = *(const float4*)(Qb + r * NK + c4);
        Qs[(c4 + 0) * QSTR + r] = v.x;
        Qs[(c4 + 1) * QSTR + r] = v.y;
        Qs[(c4 + 2) * QSTR + r] = v.z;
        Qs[(c4 + 3) * QSTR + r] = v.w;
    }
    if (tid < 64) { m_s[tid] = -INFINITY; l_s[tid] = 0.f; c_s[tid] = 1.f; }

    const int tx = tid & 15, ty = tid >> 4; // S-GEMM: 4x4/thr ; PV: rows ty*4, cols tx*8

    float accz[4][8];
#pragma unroll
    for (int i = 0; i < 4; i++)
#pragma unroll
        for (int j = 0; j < 8; j++) accz[i][j] = 0.f;

    const float scale = 0.08838834764831845f;   // 1/sqrt(128)
    const int* Mb = Mg + ((size_t)b * NS + q0) * NS;

    for (int t0 = 0; t0 < NS; t0 += 64) {
        __syncthreads();
        const float* Kb = Kg + ((size_t)bh * NS + t0) * NK;
        const float* Vb = Vg + ((size_t)bh * NS + t0) * NK;
#pragma unroll
        for (int it = 0; it < 8; it++) {
            int l = tid + it * 256;
            int r = l >> 5, c4 = (l & 31) * 4;
            float4 v = *(const float4*)(Kb + r * NK + c4);
            Ks[(c4 + 0) * QSTR + r] = v.x;
            Ks[(c4 + 1) * QSTR + r] = v.y;
            Ks[(c4 + 2) * QSTR + r] = v.z;
            Ks[(c4 + 3) * QSTR + r] = v.w;
            float4 w = *(const float4*)(Vb + r * NK + c4);
            *(float4*)(Vs + r * NK + c4) = w;
        }
        __syncthreads();

        // scores S[r][t] = Q . K
        float accs[4][4];
#pragma unroll
        for (int i = 0; i < 4; i++)
#pragma unroll
            for (int j = 0; j < 4; j++) accs[i][j] = 0.f;
#pragma unroll 4
        for (int d = 0; d < NK; d++) {
            float qv[4], kv[4];
#pragma unroll
            for (int i = 0; i < 4; i++) qv[i] = Qs[d * QSTR + ty * 4 + i];
#pragma unroll
            for (int j = 0; j < 4; j++) kv[j] = Ks[d * QSTR + tx * 4 + j];
#pragma unroll
            for (int i = 0; i < 4; i++)
#pragma unroll
                for (int j = 0; j < 4; j++)
                    accs[i][j] = fmaf(qv[i], kv[j], accs[i][j]);
        }
#pragma unroll
        for (int i = 0; i < 4; i++)
#pragma unroll
            for (int j = 0; j < 4; j++)
                Ps[(ty * 4 + i) * PSTR + tx * 4 + j] = accs[i][j];
        __syncthreads();

        // online softmax: 4 lanes per row
        {
            const int r = tid >> 2, p = tid & 3;
            const int cbase = p * 16;
            const int* mrow = Mb + (size_t)r * NS + t0 + cbase;
            float sv[16];
            float lmax = -INFINITY;
#pragma unroll
            for (int j = 0; j < 16; j++) {
                float sc = Ps[r * PSTR + cbase + j] * scale;
                if (mrow[j] == 0) sc = -1.0e9f;
                sv[j] = sc;
                lmax = fmaxf(lmax, sc);
            }
            lmax = fmaxf(lmax, __shfl_xor_sync(0xffffffffu, lmax, 1));
            lmax = fmaxf(lmax, __shfl_xor_sync(0xffffffffu, lmax, 2));
            float mold = m_s[r];
            float mnew = fmaxf(mold, lmax);
            float lsum = 0.f;
#pragma unroll
            for (int j = 0; j < 16; j++) {
                float e = __expf(sv[j] - mnew);
                Ps[r * PSTR + cbase + j] = e;
                lsum += e;
            }
            lsum += __shfl_xor_sync(0xffffffffu, lsum, 1);
            lsum += __shfl_xor_sync(0xffffffffu, lsum, 2);
            if (p == 0) {
                float corr = __expf(mold - mnew);
                m_s[r] = mnew;
                l_s[r] = l_s[r] * corr + lsum;
                c_s[r] = corr;
            }
        }
        __syncthreads();

        // rescale + accumulate P @ V
#pragma unroll
        for (int i = 0; i < 4; i++) {
            float corr = c_s[ty * 4 + i];
#pragma unroll
            for (int j = 0; j < 8; j++) accz[i][j] *= corr;
        }
#pragma unroll 2
        for (int t = 0; t < 64; t++) {
            float pv[4];
#pragma unroll
            for (int i = 0; i < 4; i++) pv[i] = Ps[(ty * 4 + i) * PSTR + t];
            float4 v0 = *(const float4*)(Vs + t * NK + tx * 8);
            float4 v1 = *(const float4*)(Vs + t * NK + tx * 8 + 4);
#pragma unroll
            for (int i = 0; i < 4; i++) {
                accz[i][0] = fmaf(pv[i], v0.x, accz[i][0]);
                accz[i][1] = fmaf(pv[i], v0.y, accz[i][1]);
                accz[i][2] = fmaf(pv[i], v0.z, accz[i][2]);
                accz[i][3] = fmaf(pv[i], v0.w, accz[i][3]);
                accz[i][4] = fmaf(pv[i], v1.x, accz[i][4]);
                accz[i][5] = fmaf(pv[i], v1.y, accz[i][5]);
                accz[i][6] = fmaf(pv[i], v1.z, accz[i][6]);
                accz[i][7] = fmaf(pv[i], v1.w, accz[i][7]);
            }
        }
    }

    // epilogue: normalize and write concat-head layout [B,S,D]
#pragma unroll
    for (int i = 0; i < 4; i++) {
        int r = ty * 4 + i;
        float inv = 1.0f / l_s[r];
        float out[8];
#pragma unroll
        for (int j = 0; j < 8; j++) out[j] = accz[i][j] * inv;
        float* dst = Og + ((size_t)(b * NS + q0 + r)) * ND + h * NK + tx * 8;
        *(float4*)(dst)     = *(float4*)(out);
        *(float4*)(dst + 4) = *(float4*)(out + 4);
    }
}

// ---------------- fused residual add + LayerNorm ---------------------------
__global__ __launch_bounds__(256) void add_ln_kernel(
    const float* __restrict__ X, const float* __restrict__ R,
    const float* __restrict__ ga, const float* __restrict__ be,
    float* __restrict__ O)
{
    __shared__ float red1[8];
    __shared__ float red2[8];
    __shared__ float s_mean, s_rstd;
    const int row = blockIdx.x;
    const int tid = threadIdx.x;
    const size_t base = (size_t)row * ND;

    float4 a = *(const float4*)(X + base + tid * 4);
    float4 r = *(const float4*)(R + base + tid * 4);
    float v0 = a.x + r.x, v1 = a.y + r.y, v2 = a.z + r.z, v3 = a.w + r.w;

    float s = v0 + v1 + v2 + v3;
#pragma unroll
    for (int o = 16; o > 0; o >>= 1) s += __shfl_xor_sync(0xffffffffu, s, o);
    if ((tid & 31) == 0) red1[tid >> 5] = s;
    __syncthreads();
    if (tid == 0) {
        float t = 0.f;
#pragma unroll
        for (int i = 0; i < 8; i++) t += red1[i];
        s_mean = t * (1.0f / ND);
    }
    __syncthreads();
    const float mean = s_mean;
    float d0 = v0 - mean, d1 = v1 - mean, d2 = v2 - mean, d3 = v3 - mean;
    float q = d0 * d0 + d1 * d1 + d2 * d2 + d3 * d3;
#pragma unroll
    for (int o = 16; o > 0; o >>= 1) q += __shfl_xor_sync(0xffffffffu, q, o);
    if ((tid & 31) == 0) red2[tid >> 5] = q;
    __syncthreads();
    if (tid == 0) {
        float t = 0.f;
#pragma unroll
        for (int i = 0; i < 8; i++) t += red2[i];
        s_rstd = rsqrtf(t * (1.0f / ND) + 1e-5f);
    }
    __syncthreads();
    const float rstd = s_rstd;

    float4 g4 = *(const float4*)(ga + tid * 4);
    float4 b4 = *(const float4*)(be + tid * 4);
    float4 o4;
    o4.x = d0 * rstd * g4.x + b4.x;
    o4.y = d1 * rstd * g4.y + b4.y;
    o4.z = d2 * rstd * g4.z + b4.z;
    o4.w = d3 * rstd * g4.w + b4.w;
    *(float4*)(O + base + tid * 4) = o4;
}

// ---------------- launcher ---------------------------------------------------
extern "C" void kernel_launch(void* const* d_in, const int* in_sizes, int n_in,
                              void* d_out, int out_size) {
    (void)in_sizes; (void)n_in; (void)out_size;
    const float* x    = (const float*)d_in[0];
    const int*   mask = (const int*)  d_in[1];
    const float* wq   = (const float*)d_in[2];
    const float* bq   = (const float*)d_in[3];
    const float* wk   = (const float*)d_in[4];
    const float* bk   = (const float*)d_in[5];
    const float* wv   = (const float*)d_in[6];
    const float* bv   = (const float*)d_in[7];
    const float* wo   = (const float*)d_in[8];
    const float* bo   = (const float*)d_in[9];
    const float* w1   = (const float*)d_in[10];
    const float* b1   = (const float*)d_in[11];
    const float* w2   = (const float*)d_in[12];
    const float* b2   = (const float*)d_in[13];
    const float* l1g  = (const float*)d_in[14];
    const float* l1b  = (const float*)d_in[15];
    const float* l2g  = (const float*)d_in[16];
    const float* l2b  = (const float*)d_in[17];

    float *px, *pq, *pk, *pv, *pao, *pt1, *pt2;
    cudaGetSymbolAddress((void**)&px,  g_x);
    cudaGetSymbolAddress((void**)&pq,  g_q);
    cudaGetSymbolAddress((void**)&pk,  g_k);
    cudaGetSymbolAddress((void**)&pv,  g_v);
    cudaGetSymbolAddress((void**)&pao, g_ao);
    cudaGetSymbolAddress((void**)&pt1, g_t1);
    cudaGetSymbolAddress((void**)&pt2, g_t2);

    cudaFuncSetAttribute(attn_kernel,
                         cudaFuncAttributeMaxDynamicSharedMemorySize,
                         ATTN_SMEM_BYTES);

    copy_f4<<<(NM * ND / 4) / 256, 256>>>((const float4*)x, (float4*)px);

    for (int l = 0; l < NL; l++) {
        const size_t wof = (size_t)l * NH * ND * NK;   // qkv weights per layer
        const size_t qbf = (size_t)l * NH * NK;        // qkv biases per layer
        const size_t dof = (size_t)l * ND * ND;        // dense weights per layer
        const size_t vof = (size_t)l * ND;             // vectors per layer

        qkv_kernel<<<dim3(NH, NM / 128, 3), 256>>>(
            px, wq + wof, wk + wof, wv + wof,
            bq + qbf, bk + qbf, bv + qbf,
            pq, pk, pv);

        attn_kernel<<<dim3(NS / 64, NB * NH), 256, ATTN_SMEM_BYTES>>>(
            pq, pk, pv, mask, pao);

        gemm_kernel<<<dim3(ND / 128, NM / 128), 256>>>(pao, wo + dof, bo + vof, pt1, 0);
        add_ln_kernel<<<NM, 256>>>(px, pt1, l1g + vof, l1b + vof, px);

        gemm_kernel<<<dim3(ND / 128, NM / 128), 256>>>(px,  w1 + dof, b1 + vof, pt2, 1);
        gemm_kernel<<<dim3(ND / 128, NM / 128), 256>>>(pt2, w2 + dof, b2 + vof, pt1, 0);

        float* dst = (l == NL - 1) ? (float*)d_out : px;
        add_ln_kernel<<<NM, 256>>>(px, pt1, l2g + vof, l2b + vof, dst);
    }
}

// round 2
// speedup vs baseline: 3.6281x; 3.6281x over previous
#include <cuda_runtime.h>
#include <math.h>

// Problem constants
#define NB 4
#define NS 2048
#define ND 1024
#define NH 8
#define NK 128
#define NL 4
#define NM (NB*NS)

// ---------------- scratch ----------------------------------------------------
__device__ float g_x [NM*ND];
__device__ float g_q [NM*ND];   // [B,H,S,NK]
__device__ float g_k [NM*ND];
__device__ float g_v [NM*ND];
__device__ float g_ao[NM*ND];   // attention out, [B,S,D]
__device__ float g_t1[NM*ND];
__device__ float g_t2[NM*ND];

// ---------------- helpers ----------------------------------------------------
__device__ __forceinline__ float gelu_exact(float x) {
    return 0.5f * x * (1.0f + erff(x * 0.7071067811865476f));
}
__device__ __forceinline__ unsigned f2tf32(float f) {
    unsigned u; asm("cvt.rna.tf32.f32 %0, %1;" : "=r"(u) : "f"(f)); return u;
}
__device__ __forceinline__ unsigned fbits(float f) { return __float_as_uint(f); }

__device__ __forceinline__ void mma_tf32(float c[4], const unsigned a[4], const unsigned b[2]) {
    asm volatile(
        "mma.sync.aligned.m16n8k8.row.col.f32.tf32.tf32.f32 "
        "{%0,%1,%2,%3}, {%4,%5,%6,%7}, {%8,%9}, {%0,%1,%2,%3};\n"
        : "+f"(c[0]), "+f"(c[1]), "+f"(c[2]), "+f"(c[3])
        : "r"(a[0]), "r"(a[1]), "r"(a[2]), "r"(a[3]), "r"(b[0]), "r"(b[1]));
}

__global__ void copy_f4(const float4* __restrict__ s, float4* __restrict__ d) {
    int i = blockIdx.x * blockDim.x + threadIdx.x;
    d[i] = s[i];
}

// ============================================================================
// Dense GEMM (tensor core, tf32): C[M x 1024] = act(A @ W + bias)
// block tile 128x128, warp tile 32x64, double-buffered smem, K-chunk 32
// ============================================================================
#define AS_STR 36
#define BS_STR 136
#define AS_SZ (128*AS_STR)
#define BS_SZ (32*BS_STR)
#define GEMM_SMEM_BYTES ((2*(AS_SZ + BS_SZ)) * 4)

__global__ __launch_bounds__(256) void gemm_tc(
    const float* __restrict__ A, const float* __restrict__ W,
    const float* __restrict__ bias, float* __restrict__ C, int act)
{
    extern __shared__ float sm[];
    float* As = sm;
    float* Bs = sm + 2 * AS_SZ;

    const int tid = threadIdx.x, lane = tid & 31, w = tid >> 5;
    const int wm = w >> 1, wn = w & 1, g = lane >> 2, t = lane & 3;
    const int m0 = blockIdx.y * 128, n0 = blockIdx.x * 128;

    float c[2][8][4];
#pragma unroll
    for (int mt = 0; mt < 2; mt++)
#pragma unroll
        for (int nt = 0; nt < 8; nt++)
#pragma unroll
            for (int i = 0; i < 4; i++) c[mt][nt][i] = 0.f;

    const int arow = tid >> 3, ac4 = (tid & 7) * 4;
    const int brow = tid >> 5, bc4 = (tid & 31) * 4;

    float4 ra[4], rb[4];
#pragma unroll
    for (int i = 0; i < 4; i++) {
        ra[i] = *(const float4*)(A + (size_t)(m0 + arow + i * 32) * ND + ac4);
        rb[i] = *(const float4*)(W + (size_t)(brow + i * 8) * ND + n0 + bc4);
    }

    int buf = 0;
    for (int k0 = 0; k0 < ND; k0 += 32) {
        // store prefetched chunk (with tf32 rounding)
#pragma unroll
        for (int i = 0; i < 4; i++) {
            uint4 ua, ub;
            ua.x = f2tf32(ra[i].x); ua.y = f2tf32(ra[i].y);
            ua.z = f2tf32(ra[i].z); ua.w = f2tf32(ra[i].w);
            *(uint4*)(&As[buf * AS_SZ + (arow + i * 32) * AS_STR + ac4]) = ua;
            ub.x = f2tf32(rb[i].x); ub.y = f2tf32(rb[i].y);
            ub.z = f2tf32(rb[i].z); ub.w = f2tf32(rb[i].w);
            *(uint4*)(&Bs[buf * BS_SZ + (brow + i * 8) * BS_STR + bc4]) = ub;
        }
        __syncthreads();
        if (k0 + 32 < ND) {
            int kn = k0 + 32;
#pragma unroll
            for (int i = 0; i < 4; i++) {
                ra[i] = *(const float4*)(A + (size_t)(m0 + arow + i * 32) * ND + kn + ac4);
                rb[i] = *(const float4*)(W + (size_t)(kn + brow + i * 8) * ND + n0 + bc4);
            }
        }
        const float* Ab = As + buf * AS_SZ;
        const float* Bb = Bs + buf * BS_SZ;
#pragma unroll
        for (int ks = 0; ks < 4; ks++) {
            unsigned a[2][4];
#pragma unroll
            for (int mt = 0; mt < 2; mt++) {
                int base = (wm * 32 + mt * 16 + g) * AS_STR + ks * 8 + t;
                a[mt][0] = fbits(Ab[base]);
                a[mt][1] = fbits(Ab[base + 8 * AS_STR]);
                a[mt][2] = fbits(Ab[base + 4]);
                a[mt][3] = fbits(Ab[base + 8 * AS_STR + 4]);
            }
#pragma unroll
            for (int nt = 0; nt < 8; nt++) {
                unsigned bf[2];
                int bb = (ks * 8 + t) * BS_STR + wn * 64 + nt * 8 + g;
                bf[0] = fbits(Bb[bb]);
                bf[1] = fbits(Bb[bb + 4 * BS_STR]);
                mma_tf32(c[0][nt], a[0], bf);
                mma_tf32(c[1][nt], a[1], bf);
            }
        }
        buf ^= 1;
    }

    // epilogue
#pragma unroll
    for (int mt = 0; mt < 2; mt++) {
        int r0 = m0 + wm * 32 + mt * 16 + g;
#pragma unroll
        for (int nt = 0; nt < 8; nt++) {
            int col = n0 + wn * 64 + nt * 8 + 2 * t;
            float b0 = bias[col], b1 = bias[col + 1];
            float v0 = c[mt][nt][0] + b0, v1 = c[mt][nt][1] + b1;
            float v2 = c[mt][nt][2] + b0, v3 = c[mt][nt][3] + b1;
            if (act) { v0 = gelu_exact(v0); v1 = gelu_exact(v1);
                       v2 = gelu_exact(v2); v3 = gelu_exact(v3); }
            float2 o0 = make_float2(v0, v1), o1 = make_float2(v2, v3);
            *(float2*)(C + (size_t)r0 * ND + col) = o0;
            *(float2*)(C + (size_t)(r0 + 8) * ND + col) = o1;
        }
    }
}

// ============================================================================
// QKV GEMM (tensor core): per-head [8192x1024] @ [1024x128], scatter to
// [B,H,S,NK], output pre-rounded to tf32 for the attention MMAs.
// ============================================================================
__global__ __launch_bounds__(256) void qkv_tc(
    const float* __restrict__ X,
    const float* __restrict__ Wq, const float* __restrict__ Wk, const float* __restrict__ Wv,
    const float* __restrict__ Bq, const float* __restrict__ Bk, const float* __restrict__ Bv,
    float* __restrict__ Qo, float* __restrict__ Ko, float* __restrict__ Vo)
{
    extern __shared__ float sm[];
    float* As = sm;
    float* Bs = sm + 2 * AS_SZ;

    const int h = blockIdx.y;
    const int m0 = blockIdx.x * 128;
    const int sel = blockIdx.z;
    const float* W  = (sel == 0) ? Wq : (sel == 1) ? Wk : Wv;
    const float* Bi = (sel == 0) ? Bq : (sel == 1) ? Bk : Bv;
    float*       O  = (sel == 0) ? Qo : (sel == 1) ? Ko : Vo;
    W  += (size_t)h * ND * NK;
    Bi += h * NK;

    const int tid = threadIdx.x, lane = tid & 31, w = tid >> 5;
    const int wm = w >> 1, wn = w & 1, g = lane >> 2, t = lane & 3;

    float c[2][8][4];
#pragma unroll
    for (int mt = 0; mt < 2; mt++)
#pragma unroll
        for (int nt = 0; nt < 8; nt++)
#pragma unroll
            for (int i = 0; i < 4; i++) c[mt][nt][i] = 0.f;

    const int arow = tid >> 3, ac4 = (tid & 7) * 4;
    const int brow = tid >> 5, bc4 = (tid & 31) * 4;

    float4 ra[4], rb[4];
#pragma unroll
    for (int i = 0; i < 4; i++) {
        ra[i] = *(const float4*)(X + (size_t)(m0 + arow + i * 32) * ND + ac4);
        rb[i] = *(const float4*)(W + (size_t)(brow + i * 8) * NK + bc4);
    }

    int buf = 0;
    for (int k0 = 0; k0 < ND; k0 += 32) {
#pragma unroll
        for (int i = 0; i < 4; i++) {
            uint4 ua, ub;
            ua.x = f2tf32(ra[i].x); ua.y = f2tf32(ra[i].y);
            ua.z = f2tf32(ra[i].z); ua.w = f2tf32(ra[i].w);
            *(uint4*)(&As[buf * AS_SZ + (arow + i * 32) * AS_STR + ac4]) = ua;
            ub.x = f2tf32(rb[i].x); ub.y = f2tf32(rb[i].y);
            ub.z = f2tf32(rb[i].z); ub.w = f2tf32(rb[i].w);
            *(uint4*)(&Bs[buf * BS_SZ + (brow + i * 8) * BS_STR + bc4]) = ub;
        }
        __syncthreads();
        if (k0 + 32 < ND) {
            int kn = k0 + 32;
#pragma unroll
            for (int i = 0; i < 4; i++) {
                ra[i] = *(const float4*)(X + (size_t)(m0 + arow + i * 32) * ND + kn + ac4);
                rb[i] = *(const float4*)(W + (size_t)(kn + brow + i * 8) * NK + bc4);
            }
        }
        const float* Ab = As + buf * AS_SZ;
        const float* Bb = Bs + buf * BS_SZ;
#pragma unroll
        for (int ks = 0; ks < 4; ks++) {
            unsigned a[2][4];
#pragma unroll
            for (int mt = 0; mt < 2; mt++) {
                int base = (wm * 32 + mt * 16 + g) * AS_STR + ks * 8 + t;
                a[mt][0] = fbits(Ab[base]);
                a[mt][1] = fbits(Ab[base + 8 * AS_STR]);
                a[mt][2] = fbits(Ab[base + 4]);
                a[mt][3] = fbits(Ab[base + 8 * AS_STR + 4]);
            }
#pragma unroll
            for (int nt = 0; nt < 8; nt++) {
                unsigned bf[2];
                int bb = (ks * 8 + t) * BS_STR + wn * 64 + nt * 8 + g;
                bf[0] = fbits(Bb[bb]);
                bf[1] = fbits(Bb[bb + 4 * BS_STR]);
                mma_tf32(c[0][nt], a[0], bf);
                mma_tf32(c[1][nt], a[1], bf);
            }
        }
        buf ^= 1;
    }

#pragma unroll
    for (int mt = 0; mt < 2; mt++) {
        int mloc = wm * 32 + mt * 16 + g;
        int m = m0 + mloc;
        int bb = m >> 11, s = m & (NS - 1);
#pragma unroll
        for (int nt = 0; nt < 8; nt++) {
            int col = wn * 64 + nt * 8 + 2 * t;
            float b0 = Bi[col], b1 = Bi[col + 1];
            float v0 = c[mt][nt][0] + b0, v1 = c[mt][nt][1] + b1;
            float v2 = c[mt][nt][2] + b0, v3 = c[mt][nt][3] + b1;
            float* d0 = O + ((size_t)(bb * NH + h) * NS + s) * NK + col;
            float2 o0 = make_float2(__uint_as_float(f2tf32(v0)), __uint_as_float(f2tf32(v1)));
            float2 o1 = make_float2(__uint_as_float(f2tf32(v2)), __uint_as_float(f2tf32(v3)));
            *(float2*)(d0) = o0;
            *(float2*)(d0 + 8 * NK) = o1;
        }
    }
}

// ============================================================================
// Flash attention, tensor core tf32. BQ=128, BT=64, D=128. 256 threads.
// ============================================================================
#define QS_STR 132
#define KS_STR 132
#define VS_STR 136
#define PS_STR 68
#define OFF_Q    0
#define OFF_K    (128*QS_STR)
#define OFF_V    (OFF_K + 64*KS_STR)
#define OFF_P    (OFF_V + 64*VS_STR)
#define OFF_M    (OFF_P + 128*PS_STR)
#define OFF_L    (OFF_M + 128)
#define OFF_C    (OFF_L + 128)
#define OFF_RMAX (OFF_C + 128)
#define OFF_RSUM (OFF_RMAX + 256)
#define ATTN_SMEM_BYTES ((OFF_RSUM + 256) * 4)

__global__ __launch_bounds__(256) void attn_tc(
    const float* __restrict__ Qg, const float* __restrict__ Kg,
    const float* __restrict__ Vg, const int* __restrict__ Mg,
    float* __restrict__ Og)
{
    extern __shared__ float sm[];
    const int tid = threadIdx.x, lane = tid & 31, w = tid >> 5;
    const int wm = w >> 1, wn = w & 1, g = lane >> 2, t = lane & 3;
    const int bh = blockIdx.y, b = bh >> 3, h = bh & 7;
    const int q0 = blockIdx.x * 128;

    // load Q tile [128 x 128]
    const float* Qb = Qg + ((size_t)bh * NS + q0) * NK;
#pragma unroll
    for (int i = 0; i < 16; i++) {
        int idx = tid + i * 256;
        int r = idx >> 5, c4 = (idx & 31) * 4;
        *(float4*)&sm[OFF_Q + r * QS_STR + c4] = *(const float4*)(Qb + (size_t)r * NK + c4);
    }
    if (tid < 128) { sm[OFF_M + tid] = -INFINITY; sm[OFF_L + tid] = 0.f; }

    float accz[2][8][4];
#pragma unroll
    for (int mt = 0; mt < 2; mt++)
#pragma unroll
        for (int nt = 0; nt < 8; nt++)
#pragma unroll
            for (int i = 0; i < 4; i++) accz[mt][nt][i] = 0.f;

    const float scale = 0.08838834764831845f;

    for (int t0 = 0; t0 < NS; t0 += 64) {
        __syncthreads();                                     // s1
        const float* Kb = Kg + ((size_t)bh * NS + t0) * NK;
        const float* Vb = Vg + ((size_t)bh * NS + t0) * NK;
#pragma unroll
        for (int i = 0; i < 8; i++) {
            int idx = tid + i * 256;
            int r = idx >> 5, c4 = (idx & 31) * 4;
            *(float4*)&sm[OFF_K + r * KS_STR + c4] = *(const float4*)(Kb + (size_t)r * NK + c4);
            *(float4*)&sm[OFF_V + r * VS_STR + c4] = *(const float4*)(Vb + (size_t)r * NK + c4);
        }
        __syncthreads();                                     // s2

        // ---- S = Q K^T  (128 x 64), warp tile 32 x 32
        float sc[2][4][4];
#pragma unroll
        for (int mt = 0; mt < 2; mt++)
#pragma unroll
            for (int nt = 0; nt < 4; nt++)
#pragma unroll
                for (int i = 0; i < 4; i++) sc[mt][nt][i] = 0.f;

#pragma unroll
        for (int ks = 0; ks < 16; ks++) {
            unsigned a[2][4];
#pragma unroll
            for (int mt = 0; mt < 2; mt++) {
                int base = OFF_Q + (wm * 32 + mt * 16 + g) * QS_STR + ks * 8 + t;
                a[mt][0] = fbits(sm[base]);
                a[mt][1] = fbits(sm[base + 8 * QS_STR]);
                a[mt][2] = fbits(sm[base + 4]);
                a[mt][3] = fbits(sm[base + 8 * QS_STR + 4]);
            }
#pragma unroll
            for (int nt = 0; nt < 4; nt++) {
                unsigned bf[2];
                int bb = OFF_K + (wn * 32 + nt * 8 + g) * KS_STR + ks * 8 + t;
                bf[0] = fbits(sm[bb]);
                bf[1] = fbits(sm[bb + 4]);
                mma_tf32(sc[0][nt], a[0], bf);
                mma_tf32(sc[1][nt], a[1], bf);
            }
        }

        // ---- mask + scale, row max
        float rmax[2][2] = {{-INFINITY, -INFINITY}, {-INFINITY, -INFINITY}};
        const size_t mbase = (size_t)b * NS * NS + (size_t)q0 * NS + t0;
#pragma unroll
        for (int mt = 0; mt < 2; mt++) {
            int rl = wm * 32 + mt * 16 + g;
#pragma unroll
            for (int nt = 0; nt < 4; nt++) {
                int cl = wn * 32 + nt * 8 + 2 * t;
                const int* mp = Mg + mbase + (size_t)rl * NS + cl;
                int2 mv0 = *(const int2*)mp;
                int2 mv1 = *(const int2*)(mp + 8 * NS);
                float s0 = (mv0.x == 0) ? -1.0e9f : sc[mt][nt][0] * scale;
                float s1 = (mv0.y == 0) ? -1.0e9f : sc[mt][nt][1] * scale;
                float s2 = (mv1.x == 0) ? -1.0e9f : sc[mt][nt][2] * scale;
                float s3 = (mv1.y == 0) ? -1.0e9f : sc[mt][nt][3] * scale;
                sc[mt][nt][0] = s0; sc[mt][nt][1] = s1;
                sc[mt][nt][2] = s2; sc[mt][nt][3] = s3;
                rmax[mt][0] = fmaxf(rmax[mt][0], fmaxf(s0, s1));
                rmax[mt][1] = fmaxf(rmax[mt][1], fmaxf(s2, s3));
            }
        }
#pragma unroll
        for (int mt = 0; mt < 2; mt++)
#pragma unroll
            for (int hh = 0; hh < 2; hh++) {
                float v = rmax[mt][hh];
                v = fmaxf(v, __shfl_xor_sync(0xffffffffu, v, 1));
                v = fmaxf(v, __shfl_xor_sync(0xffffffffu, v, 2));
                rmax[mt][hh] = v;
            }
        if (t == 0) {
#pragma unroll
            for (int mt = 0; mt < 2; mt++)
#pragma unroll
                for (int hh = 0; hh < 2; hh++)
                    sm[OFF_RMAX + wn * 128 + wm * 32 + mt * 16 + g + 8 * hh] = rmax[mt][hh];
        }
        __syncthreads();                                     // s3

        // ---- exp + row sum (using candidate new max)
        float mnew[2][2];
#pragma unroll
        for (int mt = 0; mt < 2; mt++)
#pragma unroll
            for (int hh = 0; hh < 2; hh++) {
                int r = wm * 32 + mt * 16 + g + 8 * hh;
                float tm = fmaxf(sm[OFF_RMAX + r], sm[OFF_RMAX + 128 + r]);
                mnew[mt][hh] = fmaxf(sm[OFF_M + r], tm);
            }
        float rsum[2][2] = {{0.f, 0.f}, {0.f, 0.f}};
#pragma unroll
        for (int mt = 0; mt < 2; mt++)
#pragma unroll
            for (int nt = 0; nt < 4; nt++) {
                float e0 = __expf(sc[mt][nt][0] - mnew[mt][0]);
                float e1 = __expf(sc[mt][nt][1] - mnew[mt][0]);
                float e2 = __expf(sc[mt][nt][2] - mnew[mt][1]);
                float e3 = __expf(sc[mt][nt][3] - mnew[mt][1]);
                sc[mt][nt][0] = e0; sc[mt][nt][1] = e1;
                sc[mt][nt][2] = e2; sc[mt][nt][3] = e3;
                rsum[mt][0] += e0 + e1;
                rsum[mt][1] += e2 + e3;
            }
#pragma unroll
        for (int mt = 0; mt < 2; mt++)
#pragma unroll
            for (int hh = 0; hh < 2; hh++) {
                float v = rsum[mt][hh];
                v += __shfl_xor_sync(0xffffffffu, v, 1);
                v += __shfl_xor_sync(0xffffffffu, v, 2);
                rsum[mt][hh] = v;
            }
        if (t == 0) {
#pragma unroll
            for (int mt = 0; mt < 2; mt++)
#pragma unroll
                for (int hh = 0; hh < 2; hh++)
                    sm[OFF_RSUM + wn * 128 + wm * 32 + mt * 16 + g + 8 * hh] = rsum[mt][hh];
        }
        __syncthreads();                                     // s4

        if (tid < 128) {
            int r = tid;
            float tm = fmaxf(sm[OFF_RMAX + r], sm[OFF_RMAX + 128 + r]);
            float mo = sm[OFF_M + r];
            float mn = fmaxf(mo, tm);
            float corr = __expf(mo - mn);
            sm[OFF_L + r] = sm[OFF_L + r] * corr + sm[OFF_RSUM + r] + sm[OFF_RSUM + 128 + r];
            sm[OFF_M + r] = mn;
            sm[OFF_C + r] = corr;
        }
        __syncthreads();                                     // s5

        // ---- write P (tf32), rescale running accumulators
#pragma unroll
        for (int mt = 0; mt < 2; mt++) {
            int r0 = wm * 32 + mt * 16 + g;
#pragma unroll
            for (int nt = 0; nt < 4; nt++) {
                int cl = wn * 32 + nt * 8 + 2 * t;
                uint2 p0, p1;
                p0.x = f2tf32(sc[mt][nt][0]); p0.y = f2tf32(sc[mt][nt][1]);
                p1.x = f2tf32(sc[mt][nt][2]); p1.y = f2tf32(sc[mt][nt][3]);
                *(uint2*)&sm[OFF_P + r0 * PS_STR + cl] = p0;
                *(uint2*)&sm[OFF_P + (r0 + 8) * PS_STR + cl] = p1;
            }
        }
#pragma unroll
        for (int mt = 0; mt < 2; mt++) {
            int r0 = wm * 32 + mt * 16 + g;
            float c0 = sm[OFF_C + r0];
            float c1 = sm[OFF_C + r0 + 8];
#pragma unroll
            for (int nt = 0; nt < 8; nt++) {
                accz[mt][nt][0] *= c0; accz[mt][nt][1] *= c0;
                accz[mt][nt][2] *= c1; accz[mt][nt][3] *= c1;
            }
        }
        __syncthreads();                                     // s6

        // ---- PV: accz += P[128x64] @ V[64x128], warp tile 32x64
#pragma unroll
        for (int ks = 0; ks < 8; ks++) {
            unsigned a[2][4];
#pragma unroll
            for (int mt = 0; mt < 2; mt++) {
                int base = OFF_P + (wm * 32 + mt * 16 + g) * PS_STR + ks * 8 + t;
                a[mt][0] = fbits(sm[base]);
                a[mt][1] = fbits(sm[base + 8 * PS_STR]);
                a[mt][2] = fbits(sm[base + 4]);
                a[mt][3] = fbits(sm[base + 8 * PS_STR + 4]);
            }
#pragma unroll
            for (int nt = 0; nt < 8; nt++) {
                unsigned bf[2];
                int bb = OFF_V + (ks * 8 + t) * VS_STR + wn * 64 + nt * 8 + g;
                bf[0] = fbits(sm[bb]);
                bf[1] = fbits(sm[bb + 4 * VS_STR]);
                mma_tf32(accz[0][nt], a[0], bf);
                mma_tf32(accz[1][nt], a[1], bf);
            }
        }
    }

    // epilogue: normalize + write [B,S,D] concat-head
#pragma unroll
    for (int mt = 0; mt < 2; mt++) {
        int r0 = wm * 32 + mt * 16 + g;
        float inv0 = 1.0f / sm[OFF_L + r0];
        float inv1 = 1.0f / sm[OFF_L + r0 + 8];
#pragma unroll
        for (int nt = 0; nt < 8; nt++) {
            int col = wn * 64 + nt * 8 + 2 * t;
            float2 o0 = make_float2(accz[mt][nt][0] * inv0, accz[mt][nt][1] * inv0);
            float2 o1 = make_float2(accz[mt][nt][2] * inv1, accz[mt][nt][3] * inv1);
            float* d0 = Og + ((size_t)(b * NS + q0 + r0)) * ND + h * NK + col;
            *(float2*)(d0) = o0;
            *(float2*)(d0 + 8 * ND) = o1;
        }
    }
}

// ---------------- fused residual add + LayerNorm ---------------------------
__global__ __launch_bounds__(256) void add_ln_kernel(
    const float* __restrict__ X, const float* __restrict__ R,
    const float* __restrict__ ga, const float* __restrict__ be,
    float* __restrict__ O)
{
    __shared__ float red1[8];
    __shared__ float red2[8];
    __shared__ float s_mean, s_rstd;
    const int row = blockIdx.x;
    const int tid = threadIdx.x;
    const size_t base = (size_t)row * ND;

    float4 a = *(const float4*)(X + base + tid * 4);
    float4 r = *(const float4*)(R + base + tid * 4);
    float v0 = a.x + r.x, v1 = a.y + r.y, v2 = a.z + r.z, v3 = a.w + r.w;

    float s = v0 + v1 + v2 + v3;
#pragma unroll
    for (int o = 16; o > 0; o >>= 1) s += __shfl_xor_sync(0xffffffffu, s, o);
    if ((tid & 31) == 0) red1[tid >> 5] = s;
    __syncthreads();
    if (tid == 0) {
        float tt = 0.f;
#pragma unroll
        for (int i = 0; i < 8; i++) tt += red1[i];
        s_mean = tt * (1.0f / ND);
    }
    __syncthreads();
    const float mean = s_mean;
    float d0 = v0 - mean, d1 = v1 - mean, d2 = v2 - mean, d3 = v3 - mean;
    float q = d0 * d0 + d1 * d1 + d2 * d2 + d3 * d3;
#pragma unroll
    for (int o = 16; o > 0; o >>= 1) q += __shfl_xor_sync(0xffffffffu, q, o);
    if ((tid & 31) == 0) red2[tid >> 5] = q;
    __syncthreads();
    if (tid == 0) {
        float tt = 0.f;
#pragma unroll
        for (int i = 0; i < 8; i++) tt += red2[i];
        s_rstd = rsqrtf(tt * (1.0f / ND) + 1e-5f);
    }
    __syncthreads();
    const float rstd = s_rstd;

    float4 g4 = *(const float4*)(ga + tid * 4);
    float4 b4 = *(const float4*)(be + tid * 4);
    float4 o4;
    o4.x = d0 * rstd * g4.x + b4.x;
    o4.y = d1 * rstd * g4.y + b4.y;
    o4.z = d2 * rstd * g4.z + b4.z;
    o4.w = d3 * rstd * g4.w + b4.w;
    *(float4*)(O + base + tid * 4) = o4;
}

// ---------------- launcher ---------------------------------------------------
extern "C" void kernel_launch(void* const* d_in, const int* in_sizes, int n_in,
                              void* d_out, int out_size) {
    (void)in_sizes; (void)n_in; (void)out_size;
    const float* x    = (const float*)d_in[0];
    const int*   mask = (const int*)  d_in[1];
    const float* wq   = (const float*)d_in[2];
    const float* bq   = (const float*)d_in[3];
    const float* wk   = (const float*)d_in[4];
    const float* bk   = (const float*)d_in[5];
    const float* wv   = (const float*)d_in[6];
    const float* bv   = (const float*)d_in[7];
    const float* wo   = (const float*)d_in[8];
    const float* bo   = (const float*)d_in[9];
    const float* w1   = (const float*)d_in[10];
    const float* b1   = (const float*)d_in[11];
    const float* w2   = (const float*)d_in[12];
    const float* b2   = (const float*)d_in[13];
    const float* l1g  = (const float*)d_in[14];
    const float* l1b  = (const float*)d_in[15];
    const float* l2g  = (const float*)d_in[16];
    const float* l2b  = (const float*)d_in[17];

    float *px, *pq, *pk, *pv, *pao, *pt1, *pt2;
    cudaGetSymbolAddress((void**)&px,  g_x);
    cudaGetSymbolAddress((void**)&pq,  g_q);
    cudaGetSymbolAddress((void**)&pk,  g_k);
    cudaGetSymbolAddress((void**)&pv,  g_v);
    cudaGetSymbolAddress((void**)&pao, g_ao);
    cudaGetSymbolAddress((void**)&pt1, g_t1);
    cudaGetSymbolAddress((void**)&pt2, g_t2);

    cudaFuncSetAttribute(gemm_tc, cudaFuncAttributeMaxDynamicSharedMemorySize, GEMM_SMEM_BYTES);
    cudaFuncSetAttribute(qkv_tc,  cudaFuncAttributeMaxDynamicSharedMemorySize, GEMM_SMEM_BYTES);
    cudaFuncSetAttribute(attn_tc, cudaFuncAttributeMaxDynamicSharedMemorySize, ATTN_SMEM_BYTES);

    copy_f4<<<(NM * ND / 4) / 256, 256>>>((const float4*)x, (float4*)px);

    for (int l = 0; l < NL; l++) {
        const size_t wof = (size_t)l * NH * ND * NK;
        const size_t qbf = (size_t)l * NH * NK;
        const size_t dof = (size_t)l * ND * ND;
        const size_t vof = (size_t)l * ND;

        qkv_tc<<<dim3(NM / 128, NH, 3), 256, GEMM_SMEM_BYTES>>>(
            px, wq + wof, wk + wof, wv + wof,
            bq + qbf, bk + qbf, bv + qbf,
            pq, pk, pv);

        attn_tc<<<dim3(NS / 128, NB * NH), 256, ATTN_SMEM_BYTES>>>(
            pq, pk, pv, mask, pao);

        gemm_tc<<<dim3(ND / 128, NM / 128), 256, GEMM_SMEM_BYTES>>>(pao, wo + dof, bo + vof, pt1, 0);
        add_ln_kernel<<<NM, 256>>>(px, pt1, l1g + vof, l1b + vof, px);

        gemm_tc<<<dim3(ND / 128, NM / 128), 256, GEMM_SMEM_BYTES>>>(px,  w1 + dof, b1 + vof, pt2, 1);
        gemm_tc<<<dim3(ND / 128, NM / 128), 256, GEMM_SMEM_BYTES>>>(pt2, w2 + dof, b2 + vof, pt1, 0);

        float* dst = (l == NL - 1) ? (float*)d_out : px;
        add_ln_kernel<<<NM, 256>>>(px, pt1, l2g + vof, l2b + vof, dst);
    }
}

// round 3
// speedup vs baseline: 6.3926x; 1.7620x over previous
#include <cuda_runtime.h>
#include <cuda_fp16.h>
#include <math.h>

#define NB 4
#define NS 2048
#define ND 1024
#define NH 8
#define NK 128
#define NL 4
#define NM (NB*NS)

// ---------------- scratch ----------------------------------------------------
__device__ float  g_x  [NM*ND];
__device__ float  g_t1 [NM*ND];
__device__ __half g_x16[NM*ND];
__device__ __half g_q  [NM*ND];
__device__ __half g_k  [NM*ND];
__device__ __half g_v  [NM*ND];
__device__ __half g_ao [NM*ND];
__device__ __half g_h  [NM*ND];

// ---------------- helpers ----------------------------------------------------
__device__ __forceinline__ float gelu_exact(float x) {
    return 0.5f * x * (1.0f + erff(x * 0.7071067811865476f));
}
__device__ __forceinline__ unsigned sptr(const void* p) {
    return (unsigned)__cvta_generic_to_shared(p);
}
__device__ __forceinline__ unsigned h2pack(float x, float y) {
    __half2 h = __floats2half2_rn(x, y);
    return *(unsigned*)&h;
}
__device__ __forceinline__ void ldsm4(unsigned r[4], unsigned a) {
    asm volatile("ldmatrix.sync.aligned.m8n8.x4.shared.b16 {%0,%1,%2,%3}, [%4];\n"
        : "=r"(r[0]), "=r"(r[1]), "=r"(r[2]), "=r"(r[3]) : "r"(a));
}
__device__ __forceinline__ void ldsm4t(unsigned r[4], unsigned a) {
    asm volatile("ldmatrix.sync.aligned.m8n8.x4.trans.shared.b16 {%0,%1,%2,%3}, [%4];\n"
        : "=r"(r[0]), "=r"(r[1]), "=r"(r[2]), "=r"(r[3]) : "r"(a));
}
__device__ __forceinline__ void mma16816(float c[4], const unsigned a[4],
                                         unsigned b0, unsigned b1) {
    asm volatile("mma.sync.aligned.m16n8k16.row.col.f32.f16.f16.f32 "
        "{%0,%1,%2,%3}, {%4,%5,%6,%7}, {%8,%9}, {%0,%1,%2,%3};\n"
        : "+f"(c[0]), "+f"(c[1]), "+f"(c[2]), "+f"(c[3])
        : "r"(a[0]), "r"(a[1]), "r"(a[2]), "r"(a[3]), "r"(b0), "r"(b1));
}

__global__ void copy_in(const float4* __restrict__ s, float4* __restrict__ dx,
                        uint2* __restrict__ dh) {
    int i = blockIdx.x * blockDim.x + threadIdx.x;
    float4 v = s[i];
    dx[i] = v;
    uint2 hh; hh.x = h2pack(v.x, v.y); hh.y = h2pack(v.z, v.w);
    dh[i] = hh;
}

// ============================================================================
// Dense GEMM fp16: C = act(A(h) @ W(f32->h) + bias). 128x128 block, 8 warps
// ============================================================================
#define GA_STR 40
#define GB_STR 136
#define GA_SZ (128*GA_STR)
#define GB_SZ (32*GB_STR)
#define GEMM_SMEM_BYTES ((2*(GA_SZ+GB_SZ))*2)

__global__ __launch_bounds__(256) void gemm_f16(
    const __half* __restrict__ A, const float* __restrict__ W,
    const float* __restrict__ bias, float* __restrict__ Cf,
    __half* __restrict__ Ch, int act, int outHalf)
{
    extern __shared__ __half smh[];
    __half* As = smh;
    __half* Bs = smh + 2 * GA_SZ;

    const int tid = threadIdx.x, lane = tid & 31, w = tid >> 5;
    const int wm = w >> 1, wn = w & 1, g = lane >> 2, t = lane & 3;
    const int m0 = blockIdx.y * 128, n0 = blockIdx.x * 128;

    float c[2][8][4];
#pragma unroll
    for (int mt = 0; mt < 2; mt++)
#pragma unroll
        for (int nt = 0; nt < 8; nt++)
#pragma unroll
            for (int i = 0; i < 4; i++) c[mt][nt][i] = 0.f;

    const int ar = tid >> 2, ac8 = (tid & 3) * 8;
    const int br = tid >> 5, bc4 = (tid & 31) * 4;

    uint4 ra[2]; float4 rb[4];
#pragma unroll
    for (int i = 0; i < 2; i++)
        ra[i] = *(const uint4*)(A + (size_t)(m0 + ar + i * 64) * ND + ac8);
#pragma unroll
    for (int i = 0; i < 4; i++)
        rb[i] = *(const float4*)(W + (size_t)(br + i * 8) * ND + n0 + bc4);

    int buf = 0;
    for (int k0 = 0; k0 < ND; k0 += 32) {
#pragma unroll
        for (int i = 0; i < 2; i++)
            *(uint4*)&As[buf * GA_SZ + (ar + i * 64) * GA_STR + ac8] = ra[i];
#pragma unroll
        for (int i = 0; i < 4; i++) {
            uint2 bb;
            bb.x = h2pack(rb[i].x, rb[i].y);
            bb.y = h2pack(rb[i].z, rb[i].w);
            *(uint2*)&Bs[buf * GB_SZ + (br + i * 8) * GB_STR + bc4] = bb;
        }
        __syncthreads();
        if (k0 + 32 < ND) {
            int kn = k0 + 32;
#pragma unroll
            for (int i = 0; i < 2; i++)
                ra[i] = *(const uint4*)(A + (size_t)(m0 + ar + i * 64) * ND + kn + ac8);
#pragma unroll
            for (int i = 0; i < 4; i++)
                rb[i] = *(const float4*)(W + (size_t)(kn + br + i * 8) * ND + n0 + bc4);
        }
        unsigned abase = sptr(As + buf * GA_SZ) +
            ((wm * 32 + (lane & 15)) * GA_STR + (lane >> 4) * 8) * 2;
        unsigned bbase = sptr(Bs + buf * GB_SZ) +
            ((lane & 15) * GB_STR + wn * 64 + (lane >> 4) * 8) * 2;
#pragma unroll
        for (int ks = 0; ks < 2; ks++) {
            unsigned a0[4], a1[4];
            ldsm4(a0, abase + ks * 32);
            ldsm4(a1, abase + 16 * GA_STR * 2 + ks * 32);
            unsigned bf[4][4];
#pragma unroll
            for (int p = 0; p < 4; p++)
                ldsm4t(bf[p], bbase + ks * 16 * GB_STR * 2 + p * 32);
#pragma unroll
            for (int p = 0; p < 4; p++) {
                mma16816(c[0][2 * p],     a0, bf[p][0], bf[p][1]);
                mma16816(c[0][2 * p + 1], a0, bf[p][2], bf[p][3]);
                mma16816(c[1][2 * p],     a1, bf[p][0], bf[p][1]);
                mma16816(c[1][2 * p + 1], a1, bf[p][2], bf[p][3]);
            }
        }
        buf ^= 1;
    }

#pragma unroll
    for (int mt = 0; mt < 2; mt++) {
        int r0 = m0 + wm * 32 + mt * 16 + g;
#pragma unroll
        for (int nt = 0; nt < 8; nt++) {
            int col = n0 + wn * 64 + nt * 8 + 2 * t;
            float b0 = bias[col], b1 = bias[col + 1];
            float v0 = c[mt][nt][0] + b0, v1 = c[mt][nt][1] + b1;
            float v2 = c[mt][nt][2] + b0, v3 = c[mt][nt][3] + b1;
            if (act) { v0 = gelu_exact(v0); v1 = gelu_exact(v1);
                       v2 = gelu_exact(v2); v3 = gelu_exact(v3); }
            if (outHalf) {
                *(unsigned*)(Ch + (size_t)r0 * ND + col)       = h2pack(v0, v1);
                *(unsigned*)(Ch + (size_t)(r0 + 8) * ND + col) = h2pack(v2, v3);
            } else {
                *(float2*)(Cf + (size_t)r0 * ND + col)       = make_float2(v0, v1);
                *(float2*)(Cf + (size_t)(r0 + 8) * ND + col) = make_float2(v2, v3);
            }
        }
    }
}

// ============================================================================
// QKV GEMM fp16: per-head [8192x1024]@[1024x128] -> scatter [B,H,S,NK] half
// ============================================================================
__global__ __launch_bounds__(256) void qkv_f16(
    const __half* __restrict__ X,
    const float* __restrict__ Wq, const float* __restrict__ Wk, const float* __restrict__ Wv,
    const float* __restrict__ Bq, const float* __restrict__ Bk, const float* __restrict__ Bv,
    __half* __restrict__ Qo, __half* __restrict__ Ko, __half* __restrict__ Vo)
{
    extern __shared__ __half smh[];
    __half* As = smh;
    __half* Bs = smh + 2 * GA_SZ;

    const int h = blockIdx.y, m0 = blockIdx.x * 128, sel = blockIdx.z;
    const float* W  = (sel == 0) ? Wq : (sel == 1) ? Wk : Wv;
    const float* Bi = (sel == 0) ? Bq : (sel == 1) ? Bk : Bv;
    __half*      O  = (sel == 0) ? Qo : (sel == 1) ? Ko : Vo;
    W  += (size_t)h * ND * NK;
    Bi += h * NK;

    const int tid = threadIdx.x, lane = tid & 31, w = tid >> 5;
    const int wm = w >> 1, wn = w & 1, g = lane >> 2, t = lane & 3;

    float c[2][8][4];
#pragma unroll
    for (int mt = 0; mt < 2; mt++)
#pragma unroll
        for (int nt = 0; nt < 8; nt++)
#pragma unroll
            for (int i = 0; i < 4; i++) c[mt][nt][i] = 0.f;

    const int ar = tid >> 2, ac8 = (tid & 3) * 8;
    const int br = tid >> 5, bc4 = (tid & 31) * 4;

    uint4 ra[2]; float4 rb[4];
#pragma unroll
    for (int i = 0; i < 2; i++)
        ra[i] = *(const uint4*)(X + (size_t)(m0 + ar + i * 64) * ND + ac8);
#pragma unroll
    for (int i = 0; i < 4; i++)
        rb[i] = *(const float4*)(W + (size_t)(br + i * 8) * NK + bc4);

    int buf = 0;
    for (int k0 = 0; k0 < ND; k0 += 32) {
#pragma unroll
        for (int i = 0; i < 2; i++)
            *(uint4*)&As[buf * GA_SZ + (ar + i * 64) * GA_STR + ac8] = ra[i];
#pragma unroll
        for (int i = 0; i < 4; i++) {
            uint2 bb;
            bb.x = h2pack(rb[i].x, rb[i].y);
            bb.y = h2pack(rb[i].z, rb[i].w);
            *(uint2*)&Bs[buf * GB_SZ + (br + i * 8) * GB_STR + bc4] = bb;
        }
        __syncthreads();
        if (k0 + 32 < ND) {
            int kn = k0 + 32;
#pragma unroll
            for (int i = 0; i < 2; i++)
                ra[i] = *(const uint4*)(X + (size_t)(m0 + ar + i * 64) * ND + kn + ac8);
#pragma unroll
            for (int i = 0; i < 4; i++)
                rb[i] = *(const float4*)(W + (size_t)(kn + br + i * 8) * NK + bc4);
        }
        unsigned abase = sptr(As + buf * GA_SZ) +
            ((wm * 32 + (lane & 15)) * GA_STR + (lane >> 4) * 8) * 2;
        unsigned bbase = sptr(Bs + buf * GB_SZ) +
            ((lane & 15) * GB_STR + wn * 64 + (lane >> 4) * 8) * 2;
#pragma unroll
        for (int ks = 0; ks < 2; ks++) {
            unsigned a0[4], a1[4];
            ldsm4(a0, abase + ks * 32);
            ldsm4(a1, abase + 16 * GA_STR * 2 + ks * 32);
            unsigned bf[4][4];
#pragma unroll
            for (int p = 0; p < 4; p++)
                ldsm4t(bf[p], bbase + ks * 16 * GB_STR * 2 + p * 32);
#pragma unroll
            for (int p = 0; p < 4; p++) {
                mma16816(c[0][2 * p],     a0, bf[p][0], bf[p][1]);
                mma16816(c[0][2 * p + 1], a0, bf[p][2], bf[p][3]);
                mma16816(c[1][2 * p],     a1, bf[p][0], bf[p][1]);
                mma16816(c[1][2 * p + 1], a1, bf[p][2], bf[p][3]);
            }
        }
        buf ^= 1;
    }

#pragma unroll
    for (int mt = 0; mt < 2; mt++) {
        int m = m0 + wm * 32 + mt * 16 + g;
        int bb = m >> 11, s = m & (NS - 1);
#pragma unroll
        for (int nt = 0; nt < 8; nt++) {
            int col = wn * 64 + nt * 8 + 2 * t;
            float b0 = Bi[col], b1 = Bi[col + 1];
            __half* d0 = O + ((size_t)(bb * NH + h) * NS + s) * NK + col;
            *(unsigned*)(d0)          = h2pack(c[mt][nt][0] + b0, c[mt][nt][1] + b1);
            *(unsigned*)(d0 + 8 * NK) = h2pack(c[mt][nt][2] + b0, c[mt][nt][3] + b1);
        }
    }
}

// ============================================================================
// Flash attention fp16 tensor core. BQ=128, BT=64, D=128, 256 threads.
// ============================================================================
#define QS_STR 136
#define KS_STR 136
#define VS_STR 136
#define PS_STR 72
#define OFF_Q 0
#define OFF_K (128*QS_STR)
#define OFF_V (OFF_K + 64*KS_STR)
#define OFF_P (OFF_V + 64*VS_STR)
#define HALF_END (OFF_P + 128*PS_STR)
#define SOFF_M    0
#define SOFF_L    128
#define SOFF_RMAX 256
#define SOFF_RSUM 512
#define ATTN_SMEM_BYTES (HALF_END*2 + 768*4)

__global__ __launch_bounds__(256) void attn_f16(
    const __half* __restrict__ Qg, const __half* __restrict__ Kg,
    const __half* __restrict__ Vg, const int* __restrict__ Mg,
    __half* __restrict__ Og)
{
    extern __shared__ __half smh[];
    float* smf = (float*)((char*)smh + HALF_END * 2);

    const int tid = threadIdx.x, lane = tid & 31, w = tid >> 5;
    const int wm = w >> 1, wn = w & 1, g = lane >> 2, t = lane & 3;
    const int bh = blockIdx.y, b = bh >> 3, h = bh & 7;
    const int q0 = blockIdx.x * 128;

    // load Q tile [128 x 128] halfs
    const __half* Qb = Qg + ((size_t)bh * NS + q0) * NK;
#pragma unroll
    for (int i = 0; i < 8; i++) {
        int idx = tid + i * 256;
        int r = idx >> 4, c8 = (idx & 15) * 8;
        *(uint4*)&smh[OFF_Q + r * QS_STR + c8] = *(const uint4*)(Qb + (size_t)r * NK + c8);
    }
    if (tid < 128) { smf[SOFF_M + tid] = -INFINITY; smf[SOFF_L + tid] = 0.f; }

    float accz[2][8][4];
#pragma unroll
    for (int mt = 0; mt < 2; mt++)
#pragma unroll
        for (int nt = 0; nt < 8; nt++)
#pragma unroll
            for (int i = 0; i < 4; i++) accz[mt][nt][i] = 0.f;

    const float scale = 0.08838834764831845f;

    for (int t0 = 0; t0 < NS; t0 += 64) {
        __syncthreads();                                     // s1
        const __half* Kb = Kg + ((size_t)bh * NS + t0) * NK;
        const __half* Vb = Vg + ((size_t)bh * NS + t0) * NK;
#pragma unroll
        for (int i = 0; i < 4; i++) {
            int idx = tid + i * 256;
            int r = idx >> 4, c8 = (idx & 15) * 8;
            *(uint4*)&smh[OFF_K + r * KS_STR + c8] = *(const uint4*)(Kb + (size_t)r * NK + c8);
            *(uint4*)&smh[OFF_V + r * VS_STR + c8] = *(const uint4*)(Vb + (size_t)r * NK + c8);
        }
        __syncthreads();                                     // s2

        // ---- S = Q K^T (128x64), warp tile 32x32
        float sc[2][4][4];
#pragma unroll
        for (int mt = 0; mt < 2; mt++)
#pragma unroll
            for (int nt = 0; nt < 4; nt++)
#pragma unroll
                for (int i = 0; i < 4; i++) sc[mt][nt][i] = 0.f;

        {
            unsigned qbase = sptr(smh + OFF_Q) +
                ((wm * 32 + (lane & 15)) * QS_STR + (lane >> 4) * 8) * 2;
            unsigned kbase = sptr(smh + OFF_K) +
                (((lane >> 4) * 8 + (lane & 7)) * KS_STR + ((lane >> 3) & 1) * 8) * 2;
#pragma unroll
            for (int ks = 0; ks < 8; ks++) {
                unsigned a0[4], a1[4];
                ldsm4(a0, qbase + ks * 32);
                ldsm4(a1, qbase + 16 * QS_STR * 2 + ks * 32);
                unsigned kb[2][4];
#pragma unroll
                for (int p = 0; p < 2; p++)
                    ldsm4(kb[p], kbase + (wn * 32 + p * 16) * KS_STR * 2 + ks * 32);
#pragma unroll
                for (int p = 0; p < 2; p++) {
                    mma16816(sc[0][2 * p],     a0, kb[p][0], kb[p][1]);
                    mma16816(sc[0][2 * p + 1], a0, kb[p][2], kb[p][3]);
                    mma16816(sc[1][2 * p],     a1, kb[p][0], kb[p][1]);
                    mma16816(sc[1][2 * p + 1], a1, kb[p][2], kb[p][3]);
                }
            }
        }

        // ---- mask + scale, row max
        float rmax[2][2] = {{-INFINITY, -INFINITY}, {-INFINITY, -INFINITY}};
        const size_t mbase = (size_t)b * NS * NS + (size_t)q0 * NS + t0;
#pragma unroll
        for (int mt = 0; mt < 2; mt++) {
            int rl = wm * 32 + mt * 16 + g;
#pragma unroll
            for (int nt = 0; nt < 4; nt++) {
                int cl = wn * 32 + nt * 8 + 2 * t;
                const int* mp = Mg + mbase + (size_t)rl * NS + cl;
                int2 mv0 = *(const int2*)mp;
                int2 mv1 = *(const int2*)(mp + 8 * NS);
                float s0 = (mv0.x == 0) ? -1.0e9f : sc[mt][nt][0] * scale;
                float s1 = (mv0.y == 0) ? -1.0e9f : sc[mt][nt][1] * scale;
                float s2 = (mv1.x == 0) ? -1.0e9f : sc[mt][nt][2] * scale;
                float s3 = (mv1.y == 0) ? -1.0e9f : sc[mt][nt][3] * scale;
                sc[mt][nt][0] = s0; sc[mt][nt][1] = s1;
                sc[mt][nt][2] = s2; sc[mt][nt][3] = s3;
                rmax[mt][0] = fmaxf(rmax[mt][0], fmaxf(s0, s1));
                rmax[mt][1] = fmaxf(rmax[mt][1], fmaxf(s2, s3));
            }
        }
#pragma unroll
        for (int mt = 0; mt < 2; mt++)
#pragma unroll
            for (int hh = 0; hh < 2; hh++) {
                float v = rmax[mt][hh];
                v = fmaxf(v, __shfl_xor_sync(0xffffffffu, v, 1));
                v = fmaxf(v, __shfl_xor_sync(0xffffffffu, v, 2));
                rmax[mt][hh] = v;
            }
        if (t == 0) {
#pragma unroll
            for (int mt = 0; mt < 2; mt++)
#pragma unroll
                for (int hh = 0; hh < 2; hh++)
                    smf[SOFF_RMAX + wn * 128 + wm * 32 + mt * 16 + g + 8 * hh] = rmax[mt][hh];
        }
        __syncthreads();                                     // s3

        // ---- exp + rowsum + P write + accz rescale (corr computed locally)
        float mold[2][2], mnew[2][2];
#pragma unroll
        for (int mt = 0; mt < 2; mt++)
#pragma unroll
            for (int hh = 0; hh < 2; hh++) {
                int r = wm * 32 + mt * 16 + g + 8 * hh;
                float tm = fmaxf(smf[SOFF_RMAX + r], smf[SOFF_RMAX + 128 + r]);
                mold[mt][hh] = smf[SOFF_M + r];
                mnew[mt][hh] = fmaxf(mold[mt][hh], tm);
            }
        float rsum[2][2] = {{0.f, 0.f}, {0.f, 0.f}};
#pragma unroll
        for (int mt = 0; mt < 2; mt++)
#pragma unroll
            for (int nt = 0; nt < 4; nt++) {
                float e0 = __expf(sc[mt][nt][0] - mnew[mt][0]);
                float e1 = __expf(sc[mt][nt][1] - mnew[mt][0]);
                float e2 = __expf(sc[mt][nt][2] - mnew[mt][1]);
                float e3 = __expf(sc[mt][nt][3] - mnew[mt][1]);
                rsum[mt][0] += e0 + e1;
                rsum[mt][1] += e2 + e3;
                int r0 = wm * 32 + mt * 16 + g;
                int cl = wn * 32 + nt * 8 + 2 * t;
                *(unsigned*)&smh[OFF_P + r0 * PS_STR + cl]       = h2pack(e0, e1);
                *(unsigned*)&smh[OFF_P + (r0 + 8) * PS_STR + cl] = h2pack(e2, e3);
            }
#pragma unroll
        for (int mt = 0; mt < 2; mt++)
#pragma unroll
            for (int hh = 0; hh < 2; hh++) {
                float v = rsum[mt][hh];
                v += __shfl_xor_sync(0xffffffffu, v, 1);
                v += __shfl_xor_sync(0xffffffffu, v, 2);
                rsum[mt][hh] = v;
            }
        if (t == 0) {
#pragma unroll
            for (int mt = 0; mt < 2; mt++)
#pragma unroll
                for (int hh = 0; hh < 2; hh++)
                    smf[SOFF_RSUM + wn * 128 + wm * 32 + mt * 16 + g + 8 * hh] = rsum[mt][hh];
        }
#pragma unroll
        for (int mt = 0; mt < 2; mt++) {
            float c0 = __expf(mold[mt][0] - mnew[mt][0]);
            float c1 = __expf(mold[mt][1] - mnew[mt][1]);
#pragma unroll
            for (int nt = 0; nt < 8; nt++) {
                accz[mt][nt][0] *= c0; accz[mt][nt][1] *= c0;
                accz[mt][nt][2] *= c1; accz[mt][nt][3] *= c1;
            }
        }
        __syncthreads();                                     // s4

        if (tid < 128) {
            int r = tid;
            float tm = fmaxf(smf[SOFF_RMAX + r], smf[SOFF_RMAX + 128 + r]);
            float mo = smf[SOFF_M + r];
            float mn = fmaxf(mo, tm);
            float corr = __expf(mo - mn);
            smf[SOFF_L + r] = smf[SOFF_L + r] * corr +
                              smf[SOFF_RSUM + r] + smf[SOFF_RSUM + 128 + r];
            smf[SOFF_M + r] = mn;
        }

        // ---- PV: accz += P[128x64] @ V[64x128]
        {
            unsigned pbase = sptr(smh + OFF_P) +
                ((wm * 32 + (lane & 15)) * PS_STR + (lane >> 4) * 8) * 2;
            unsigned vbase = sptr(smh + OFF_V) +
                ((lane & 15) * VS_STR + wn * 64 + (lane >> 4) * 8) * 2;
#pragma unroll
            for (int ks = 0; ks < 4; ks++) {
                unsigned a0[4], a1[4];
                ldsm4(a0, pbase + ks * 32);
                ldsm4(a1, pbase + 16 * PS_STR * 2 + ks * 32);
                unsigned vf[4][4];
#pragma unroll
                for (int p = 0; p < 4; p++)
                    ldsm4t(vf[p], vbase + ks * 16 * VS_STR * 2 + p * 32);
#pragma unroll
                for (int p = 0; p < 4; p++) {
                    mma16816(accz[0][2 * p],     a0, vf[p][0], vf[p][1]);
                    mma16816(accz[0][2 * p + 1], a0, vf[p][2], vf[p][3]);
                    mma16816(accz[1][2 * p],     a1, vf[p][0], vf[p][1]);
                    mma16816(accz[1][2 * p + 1], a1, vf[p][2], vf[p][3]);
                }
            }
        }
    }

    __syncthreads();
    // epilogue: normalize + write [B,S,D] half
#pragma unroll
    for (int mt = 0; mt < 2; mt++) {
        int r0 = wm * 32 + mt * 16 + g;
        float inv0 = 1.0f / smf[SOFF_L + r0];
        float inv1 = 1.0f / smf[SOFF_L + r0 + 8];
#pragma unroll
        for (int nt = 0; nt < 8; nt++) {
            int col = wn * 64 + nt * 8 + 2 * t;
            __half* d0 = Og + ((size_t)(b * NS + q0 + r0)) * ND + h * NK + col;
            *(unsigned*)(d0)          = h2pack(accz[mt][nt][0] * inv0, accz[mt][nt][1] * inv0);
            *(unsigned*)(d0 + 8 * ND) = h2pack(accz[mt][nt][2] * inv1, accz[mt][nt][3] * inv1);
        }
    }
}

// ---------------- fused residual add + LayerNorm (f32 + f16 outputs) --------
__global__ __launch_bounds__(256) void add_ln_kernel(
    const float* __restrict__ X, const float* __restrict__ R,
    const float* __restrict__ ga, const float* __restrict__ be,
    float* __restrict__ O, __half* __restrict__ O16)
{
    __shared__ float red1[8];
    __shared__ float red2[8];
    __shared__ float s_mean, s_rstd;
    const int row = blockIdx.x;
    const int tid = threadIdx.x;
    const size_t base = (size_t)row * ND;

    float4 a = *(const float4*)(X + base + tid * 4);
    float4 r = *(const float4*)(R + base + tid * 4);
    float v0 = a.x + r.x, v1 = a.y + r.y, v2 = a.z + r.z, v3 = a.w + r.w;

    float s = v0 + v1 + v2 + v3;
#pragma unroll
    for (int o = 16; o > 0; o >>= 1) s += __shfl_xor_sync(0xffffffffu, s, o);
    if ((tid & 31) == 0) red1[tid >> 5] = s;
    __syncthreads();
    if (tid == 0) {
        float tt = 0.f;
#pragma unroll
        for (int i = 0; i < 8; i++) tt += red1[i];
        s_mean = tt * (1.0f / ND);
    }
    __syncthreads();
    const float mean = s_mean;
    float d0 = v0 - mean, d1 = v1 - mean, d2 = v2 - mean, d3 = v3 - mean;
    float q = d0 * d0 + d1 * d1 + d2 * d2 + d3 * d3;
#pragma unroll
    for (int o = 16; o > 0; o >>= 1) q += __shfl_xor_sync(0xffffffffu, q, o);
    if ((tid & 31) == 0) red2[tid >> 5] = q;
    __syncthreads();
    if (tid == 0) {
        float tt = 0.f;
#pragma unroll
        for (int i = 0; i < 8; i++) tt += red2[i];
        s_rstd = rsqrtf(tt * (1.0f / ND) + 1e-5f);
    }
    __syncthreads();
    const float rstd = s_rstd;

    float4 g4 = *(const float4*)(ga + tid * 4);
    float4 b4 = *(const float4*)(be + tid * 4);
    float4 o4;
    o4.x = d0 * rstd * g4.x + b4.x;
    o4.y = d1 * rstd * g4.y + b4.y;
    o4.z = d2 * rstd * g4.z + b4.z;
    o4.w = d3 * rstd * g4.w + b4.w;
    *(float4*)(O + base + tid * 4) = o4;
    uint2 hh; hh.x = h2pack(o4.x, o4.y); hh.y = h2pack(o4.z, o4.w);
    *(uint2*)(O16 + base + tid * 4) = hh;
}

// ---------------- launcher ---------------------------------------------------
extern "C" void kernel_launch(void* const* d_in, const int* in_sizes, int n_in,
                              void* d_out, int out_size) {
    (void)in_sizes; (void)n_in; (void)out_size;
    const float* x    = (const float*)d_in[0];
    const int*   mask = (const int*)  d_in[1];
    const float* wq   = (const float*)d_in[2];
    const float* bq   = (const float*)d_in[3];
    const float* wk   = (const float*)d_in[4];
    const float* bk   = (const float*)d_in[5];
    const float* wv   = (const float*)d_in[6];
    const float* bv   = (const float*)d_in[7];
    const float* wo   = (const float*)d_in[8];
    const float* bo   = (const float*)d_in[9];
    const float* w1   = (const float*)d_in[10];
    const float* b1   = (const float*)d_in[11];
    const float* w2   = (const float*)d_in[12];
    const float* b2   = (const float*)d_in[13];
    const float* l1g  = (const float*)d_in[14];
    const float* l1b  = (const float*)d_in[15];
    const float* l2g  = (const float*)d_in[16];
    const float* l2b  = (const float*)d_in[17];

    float *px, *pt1;
    __half *px16, *pq, *pk, *pv, *pao, *ph;
    cudaGetSymbolAddress((void**)&px,   g_x);
    cudaGetSymbolAddress((void**)&pt1,  g_t1);
    cudaGetSymbolAddress((void**)&px16, g_x16);
    cudaGetSymbolAddress((void**)&pq,   g_q);
    cudaGetSymbolAddress((void**)&pk,   g_k);
    cudaGetSymbolAddress((void**)&pv,   g_v);
    cudaGetSymbolAddress((void**)&pao,  g_ao);
    cudaGetSymbolAddress((void**)&ph,   g_h);

    cudaFuncSetAttribute(gemm_f16, cudaFuncAttributeMaxDynamicSharedMemorySize, GEMM_SMEM_BYTES);
    cudaFuncSetAttribute(qkv_f16,  cudaFuncAttributeMaxDynamicSharedMemorySize, GEMM_SMEM_BYTES);
    cudaFuncSetAttribute(attn_f16, cudaFuncAttributeMaxDynamicSharedMemorySize, ATTN_SMEM_BYTES);

    copy_in<<<(NM * ND / 4) / 256, 256>>>((const float4*)x, (float4*)px, (uint2*)px16);

    for (int l = 0; l < NL; l++) {
        const size_t wof = (size_t)l * NH * ND * NK;
        const size_t qbf = (size_t)l * NH * NK;
        const size_t dof = (size_t)l * ND * ND;
        const size_t vof = (size_t)l * ND;

        qkv_f16<<<dim3(NM / 128, NH, 3), 256, GEMM_SMEM_BYTES>>>(
            px16, wq + wof, wk + wof, wv + wof,
            bq + qbf, bk + qbf, bv + qbf,
            pq, pk, pv);

        attn_f16<<<dim3(NS / 128, NB * NH), 256, ATTN_SMEM_BYTES>>>(
            pq, pk, pv, mask, pao);

        gemm_f16<<<dim3(ND / 128, NM / 128), 256, GEMM_SMEM_BYTES>>>(
            pao, wo + dof, bo + vof, pt1, (__half*)0, 0, 0);
        add_ln_kernel<<<NM, 256>>>(px, pt1, l1g + vof, l1b + vof, px, px16);

        gemm_f16<<<dim3(ND / 128, NM / 128), 256, GEMM_SMEM_BYTES>>>(
            px16, w1 + dof, b1 + vof, (float*)0, ph, 1, 1);
        gemm_f16<<<dim3(ND / 128, NM / 128), 256, GEMM_SMEM_BYTES>>>(
            ph, w2 + dof, b2 + vof, pt1, (__half*)0, 0, 0);

        float* dst = (l == NL - 1) ? (float*)d_out : px;
        add_ln_kernel<<<NM, 256>>>(px, pt1, l2g + vof, l2b + vof, dst, px16);
    }
}

// round 5
// speedup vs baseline: 6.6640x; 1.0425x over previous
#include <cuda_runtime.h>
#include <cuda_fp16.h>
#include <math.h>
#include <stdint.h>

#define NB 4
#define NS 2048
#define ND 1024
#define NH 8
#define NK 128
#define NL 4
#define NM (NB*NS)

// ---------------- scratch ----------------------------------------------------
__device__ float  g_x  [NM*ND];
__device__ float  g_t1 [NM*ND];
__device__ __half g_x16[NM*ND];
__device__ __half g_q  [NM*ND];
__device__ __half g_k  [NM*ND];
__device__ __half g_v  [NM*ND];
__device__ __half g_ao [NM*ND];
__device__ __half g_h  [NM*ND];
__device__ __half g_wtd[12*ND*ND];   // dense weights transposed [l][3][N][K] f16
__device__ __half g_wtq[12*ND*ND];   // qkv weights  transposed [l][3][H*128][K] f16

// ---------------- helpers ----------------------------------------------------
__device__ __forceinline__ float gelu_exact(float x) {
    return 0.5f * x * (1.0f + erff(x * 0.7071067811865476f));
}
__device__ __forceinline__ unsigned sptr(const void* p) {
    return (unsigned)__cvta_generic_to_shared(p);
}
__device__ __forceinline__ unsigned h2pack(float x, float y) {
    __half2 h = __floats2half2_rn(x, y);
    return *(unsigned*)&h;
}
__device__ __forceinline__ void ldsm4(unsigned r[4], unsigned a) {
    asm volatile("ldmatrix.sync.aligned.m8n8.x4.shared.b16 {%0,%1,%2,%3}, [%4];\n"
        : "=r"(r[0]), "=r"(r[1]), "=r"(r[2]), "=r"(r[3]) : "r"(a));
}
__device__ __forceinline__ void ldsm4t(unsigned r[4], unsigned a) {
    asm volatile("ldmatrix.sync.aligned.m8n8.x4.trans.shared.b16 {%0,%1,%2,%3}, [%4];\n"
        : "=r"(r[0]), "=r"(r[1]), "=r"(r[2]), "=r"(r[3]) : "r"(a));
}
__device__ __forceinline__ void mma16816(float c[4], const unsigned a[4],
                                         unsigned b0, unsigned b1) {
    asm volatile("mma.sync.aligned.m16n8k16.row.col.f32.f16.f16.f32 "
        "{%0,%1,%2,%3}, {%4,%5,%6,%7}, {%8,%9}, {%0,%1,%2,%3};\n"
        : "+f"(c[0]), "+f"(c[1]), "+f"(c[2]), "+f"(c[3])
        : "r"(a[0]), "r"(a[1]), "r"(a[2]), "r"(a[3]), "r"(b0), "r"(b1));
}
#define CP16(dst, src) \
    asm volatile("cp.async.cg.shared.global [%0], [%1], 16;" :: "r"(dst), "l"(src) : "memory")
#define CP_COMMIT() asm volatile("cp.async.commit_group;" ::: "memory")

__global__ void copy_in(const float4* __restrict__ s, float4* __restrict__ dx,
                        uint2* __restrict__ dh) {
    int i = blockIdx.x * blockDim.x + threadIdx.x;
    float4 v = s[i];
    dx[i] = v;
    uint2 hh; hh.x = h2pack(v.x, v.y); hh.y = h2pack(v.z, v.w);
    dh[i] = hh;
}

// ---------------- weight transposes (f32 [K][N] -> f16 [N][K]) --------------
__global__ void tr_dense(const float* __restrict__ wo, const float* __restrict__ w1,
                         const float* __restrict__ w2, __half* __restrict__ dst) {
    __shared__ float tile[32][33];
    int z = blockIdx.z, l = z / 3, which = z % 3;
    const float* W = (which == 0 ? wo : which == 1 ? w1 : w2) + (size_t)l * ND * ND;
    __half* D = dst + (size_t)z * ND * ND;
    int n0 = blockIdx.x * 32, k0 = blockIdx.y * 32;
    int tx = threadIdx.x, ty = threadIdx.y;
#pragma unroll
    for (int i = 0; i < 32; i += 8)
        tile[ty + i][tx] = W[(size_t)(k0 + ty + i) * ND + n0 + tx];
    __syncthreads();
#pragma unroll
    for (int i = 0; i < 32; i += 8)
        D[(size_t)(n0 + ty + i) * ND + k0 + tx] = __float2half_rn(tile[tx][ty + i]);
}

__global__ void tr_qkv(const float* __restrict__ wq, const float* __restrict__ wk,
                       const float* __restrict__ wv, __half* __restrict__ dst) {
    __shared__ float tile[32][33];
    int z = blockIdx.z;                 // (l*3+sel)*8 + h
    int l = z / 24, rem = z % 24, sel = rem / 8, h = rem % 8;
    const float* W = (sel == 0 ? wq : sel == 1 ? wk : wv) + (size_t)(l * NH + h) * ND * NK;
    __half* D = dst + (size_t)((l * 3 + sel) * 8 + h) * NK * ND;
    int n0 = blockIdx.x * 32, k0 = blockIdx.y * 32;
    int tx = threadIdx.x, ty = threadIdx.y;
#pragma unroll
    for (int i = 0; i < 32; i += 8)
        tile[ty + i][tx] = W[(size_t)(k0 + ty + i) * NK + n0 + tx];
    __syncthreads();
#pragma unroll
    for (int i = 0; i < 32; i += 8)
        D[(size_t)(n0 + ty + i) * ND + k0 + tx] = __float2half_rn(tile[tx][ty + i]);
}

// ============================================================================
// GEMM v2 (mma.sync f16): C[8192x1024] = act(A_h[M][K] @ Bt[N][K]^T + bias)
// block 128x128, 4 warps, warp tile 64x64, K-chunk 32, cp.async dbl-buffer,
// XOR-swizzled 64B rows (conflict-free ldsm + cp.async stores).
// mode: 0 = f32 out, 1 = half out + gelu, 2 = half out qkv scatter
// ============================================================================
#define BK 32
#define BUF_SZ (128*BK)                    // halfs per (A or B) buffer
#define GEMM_SMEM_BYTES (4*BUF_SZ*2)       // 32 KB

__global__ __launch_bounds__(128, 2) void gemm_v2(
    const __half* __restrict__ A, const __half* __restrict__ Bt,
    const float* __restrict__ bias, float* __restrict__ Cf,
    __half* __restrict__ Ch, int mode)
{
    extern __shared__ __half smh[];
    __half* sA = smh;                      // [2][128][32] swizzled
    __half* sB = smh + 2 * BUF_SZ;

    const int tid = threadIdx.x, lane = tid & 31, wid = tid >> 5;
    const int wm = wid >> 1, wn = wid & 1, g = lane >> 2, t = lane & 3;
    const int m0 = blockIdx.y * 128, n0 = blockIdx.x * 128;

    float c[4][8][4];
#pragma unroll
    for (int mt = 0; mt < 4; mt++)
#pragma unroll
        for (int nt = 0; nt < 8; nt++)
#pragma unroll
            for (int i = 0; i < 4; i++) c[mt][nt][i] = 0.f;

    // loader indices: each thread does 4 A + 4 B cp.async (16B each)
    const int lr = tid >> 2;               // row 0..31 (x4 strided)
    const int lu = tid & 3;                // 16B unit 0..3
    const unsigned sA0 = sptr(sA), sB0 = sptr(sB);

    // ldsm lane addressing (swizzle: unit ^= (row>>1)&3)
    const int arow = wm * 64 + (lane & 15);
    const int axor = (arow >> 1) & 3;
    const int ahi  = lane >> 4;            // 0/1
    const int brow = (lane >> 4) * 8 + (lane & 7);
    const int bxor = (brow >> 1) & 3;
    const int bhi  = (lane >> 3) & 1;

#define LOAD_CHUNK(ck, buf) do {                                              \
    int _k0 = (ck) * BK;                                                      \
    _Pragma("unroll")                                                         \
    for (int _i = 0; _i < 4; _i++) {                                          \
        int _r = lr + _i * 32;                                                \
        unsigned _sw = ((unsigned)(lu ^ ((_r >> 1) & 3))) * 16;               \
        unsigned _da = sA0 + (buf) * BUF_SZ * 2 + _r * 64 + _sw;              \
        CP16(_da, A + (size_t)(m0 + _r) * ND + _k0 + lu * 8);                 \
        unsigned _db = sB0 + (buf) * BUF_SZ * 2 + _r * 64 + _sw;              \
        CP16(_db, Bt + (size_t)(n0 + _r) * ND + _k0 + lu * 8);                \
    }                                                                         \
    CP_COMMIT();                                                              \
} while (0)

    LOAD_CHUNK(0, 0);

    for (int ck = 0; ck < ND / BK; ck++) {
        int buf = ck & 1;
        if (ck + 1 < ND / BK) {
            LOAD_CHUNK(ck + 1, buf ^ 1);
            asm volatile("cp.async.wait_group 1;" ::: "memory");
        } else {
            asm volatile("cp.async.wait_group 0;" ::: "memory");
        }
        __syncthreads();

        unsigned abuf = sA0 + buf * BUF_SZ * 2;
        unsigned bbuf = sB0 + buf * BUF_SZ * 2;
#pragma unroll
        for (int ks = 0; ks < 2; ks++) {
            unsigned akoff = ((unsigned)((ks * 2 + ahi) ^ axor)) * 16;
            unsigned a[4][4];
#pragma unroll
            for (int mt = 0; mt < 4; mt++)
                ldsm4(a[mt], abuf + (arow + mt * 16) * 64 + akoff);
            unsigned bkoff = ((unsigned)((ks * 2 + bhi) ^ bxor)) * 16;
#pragma unroll
            for (int p = 0; p < 4; p++) {
                unsigned bf[4];
                ldsm4(bf, bbuf + (brow + wn * 64 + p * 16) * 64 + bkoff);
#pragma unroll
                for (int mt = 0; mt < 4; mt++) {
                    mma16816(c[mt][2 * p],     a[mt], bf[0], bf[1]);
                    mma16816(c[mt][2 * p + 1], a[mt], bf[2], bf[3]);
                }
            }
        }
        __syncthreads();
    }

    // epilogue
#pragma unroll
    for (int mt = 0; mt < 4; mt++) {
        int r0 = m0 + wm * 64 + mt * 16 + g;
#pragma unroll
        for (int nt = 0; nt < 8; nt++) {
            int col = n0 + wn * 64 + nt * 8 + 2 * t;
            float b0 = bias[col], b1 = bias[col + 1];
            float v0 = c[mt][nt][0] + b0, v1 = c[mt][nt][1] + b1;
            float v2 = c[mt][nt][2] + b0, v3 = c[mt][nt][3] + b1;
            if (mode == 0) {
                *(float2*)(Cf + (size_t)r0 * ND + col)       = make_float2(v0, v1);
                *(float2*)(Cf + (size_t)(r0 + 8) * ND + col) = make_float2(v2, v3);
            } else if (mode == 1) {
                v0 = gelu_exact(v0); v1 = gelu_exact(v1);
                v2 = gelu_exact(v2); v3 = gelu_exact(v3);
                *(unsigned*)(Ch + (size_t)r0 * ND + col)       = h2pack(v0, v1);
                *(unsigned*)(Ch + (size_t)(r0 + 8) * ND + col) = h2pack(v2, v3);
            } else {
                int head = col >> 7, within = col & 127;
                int bb0 = r0 >> 11, s0 = r0 & (NS - 1);
                __half* d0 = Ch + ((size_t)(bb0 * NH + head) * NS + s0) * NK + within;
                *(unsigned*)(d0)          = h2pack(v0, v1);
                *(unsigned*)(d0 + 8 * NK) = h2pack(v2, v3);
            }
        }
    }
}

// ============================================================================
// Flash attention fp16 SIMT tensor core (unchanged, proven)
// ============================================================================
#define QS_STR 136
#define KS_STR 136
#define VS_STR 136
#define PS_STR 72
#define OFF_Q 0
#define OFF_K (128*QS_STR)
#define OFF_V (OFF_K + 64*KS_STR)
#define OFF_P (OFF_V + 64*VS_STR)
#define HALF_END (OFF_P + 128*PS_STR)
#define SOFF_M    0
#define SOFF_L    128
#define SOFF_RMAX 256
#define SOFF_RSUM 512
#define ATTN_SMEM_BYTES (HALF_END*2 + 768*4)

__global__ __launch_bounds__(256) void attn_f16(
    const __half* __restrict__ Qg, const __half* __restrict__ Kg,
    const __half* __restrict__ Vg, const int* __restrict__ Mg,
    __half* __restrict__ Og)
{
    extern __shared__ __half smh[];
    float* smf = (float*)((char*)smh + HALF_END * 2);

    const int tid = threadIdx.x, lane = tid & 31, w = tid >> 5;
    const int wm = w >> 1, wn = w & 1, g = lane >> 2, t = lane & 3;
    const int bh = blockIdx.y, b = bh >> 3, h = bh & 7;
    const int q0 = blockIdx.x * 128;

    const __half* Qb = Qg + ((size_t)bh * NS + q0) * NK;
#pragma unroll
    for (int i = 0; i < 8; i++) {
        int idx = tid + i * 256;
        int r = idx >> 4, c8 = (idx & 15) * 8;
        *(uint4*)&smh[OFF_Q + r * QS_STR + c8] = *(const uint4*)(Qb + (size_t)r * NK + c8);
    }
    if (tid < 128) { smf[SOFF_M + tid] = -INFINITY; smf[SOFF_L + tid] = 0.f; }

    float accz[2][8][4];
#pragma unroll
    for (int mt = 0; mt < 2; mt++)
#pragma unroll
        for (int nt = 0; nt < 8; nt++)
#pragma unroll
            for (int i = 0; i < 4; i++) accz[mt][nt][i] = 0.f;

    const float scale = 0.08838834764831845f;

    for (int t0 = 0; t0 < NS; t0 += 64) {
        __syncthreads();
        const __half* Kb = Kg + ((size_t)bh * NS + t0) * NK;
        const __half* Vb = Vg + ((size_t)bh * NS + t0) * NK;
#pragma unroll
        for (int i = 0; i < 4; i++) {
            int idx = tid + i * 256;
            int r = idx >> 4, c8 = (idx & 15) * 8;
            *(uint4*)&smh[OFF_K + r * KS_STR + c8] = *(const uint4*)(Kb + (size_t)r * NK + c8);
            *(uint4*)&smh[OFF_V + r * VS_STR + c8] = *(const uint4*)(Vb + (size_t)r * NK + c8);
        }
        __syncthreads();

        float sc[2][4][4];
#pragma unroll
        for (int mt = 0; mt < 2; mt++)
#pragma unroll
            for (int nt = 0; nt < 4; nt++)
#pragma unroll
                for (int i = 0; i < 4; i++) sc[mt][nt][i] = 0.f;

        {
            unsigned qbase = sptr(smh + OFF_Q) +
                ((wm * 32 + (lane & 15)) * QS_STR + (lane >> 4) * 8) * 2;
            unsigned kbase = sptr(smh + OFF_K) +
                (((lane >> 4) * 8 + (lane & 7)) * KS_STR + ((lane >> 3) & 1) * 8) * 2;
#pragma unroll
            for (int ks = 0; ks < 8; ks++) {
                unsigned a0[4], a1[4];
                ldsm4(a0, qbase + ks * 32);
                ldsm4(a1, qbase + 16 * QS_STR * 2 + ks * 32);
                unsigned kb[2][4];
#pragma unroll
                for (int p = 0; p < 2; p++)
                    ldsm4(kb[p], kbase + (wn * 32 + p * 16) * KS_STR * 2 + ks * 32);
#pragma unroll
                for (int p = 0; p < 2; p++) {
                    mma16816(sc[0][2 * p],     a0, kb[p][0], kb[p][1]);
                    mma16816(sc[0][2 * p + 1], a0, kb[p][2], kb[p][3]);
                    mma16816(sc[1][2 * p],     a1, kb[p][0], kb[p][1]);
                    mma16816(sc[1][2 * p + 1], a1, kb[p][2], kb[p][3]);
                }
            }
        }

        float rmax[2][2] = {{-INFINITY, -INFINITY}, {-INFINITY, -INFINITY}};
        const size_t mbase = (size_t)b * NS * NS + (size_t)q0 * NS + t0;
#pragma unroll
        for (int mt = 0; mt < 2; mt++) {
            int rl = wm * 32 + mt * 16 + g;
#pragma unroll
            for (int nt = 0; nt < 4; nt++) {
                int cl = wn * 32 + nt * 8 + 2 * t;
                const int* mp = Mg + mbase + (size_t)rl * NS + cl;
                int2 mv0 = *(const int2*)mp;
                int2 mv1 = *(const int2*)(mp + 8 * NS);
                float s0 = (mv0.x == 0) ? -1.0e9f : sc[mt][nt][0] * scale;
                float s1 = (mv0.y == 0) ? -1.0e9f : sc[mt][nt][1] * scale;
                float s2 = (mv1.x == 0) ? -1.0e9f : sc[mt][nt][2] * scale;
                float s3 = (mv1.y == 0) ? -1.0e9f : sc[mt][nt][3] * scale;
                sc[mt][nt][0] = s0; sc[mt][nt][1] = s1;
                sc[mt][nt][2] = s2; sc[mt][nt][3] = s3;
                rmax[mt][0] = fmaxf(rmax[mt][0], fmaxf(s0, s1));
                rmax[mt][1] = fmaxf(rmax[mt][1], fmaxf(s2, s3));
            }
        }
#pragma unroll
        for (int mt = 0; mt < 2; mt++)
#pragma unroll
            for (int hh = 0; hh < 2; hh++) {
                float v = rmax[mt][hh];
                v = fmaxf(v, __shfl_xor_sync(0xffffffffu, v, 1));
                v = fmaxf(v, __shfl_xor_sync(0xffffffffu, v, 2));
                rmax[mt][hh] = v;
            }
        if (t == 0) {
#pragma unroll
            for (int mt = 0; mt < 2; mt++)
#pragma unroll
                for (int hh = 0; hh < 2; hh++)
                    smf[SOFF_RMAX + wn * 128 + wm * 32 + mt * 16 + g + 8 * hh] = rmax[mt][hh];
        }
        __syncthreads();

        float mold[2][2], mnew[2][2];
#pragma unroll
        for (int mt = 0; mt < 2; mt++)
#pragma unroll
            for (int hh = 0; hh < 2; hh++) {
                int r = wm * 32 + mt * 16 + g + 8 * hh;
                float tm = fmaxf(smf[SOFF_RMAX + r], smf[SOFF_RMAX + 128 + r]);
                mold[mt][hh] = smf[SOFF_M + r];
                mnew[mt][hh] = fmaxf(mold[mt][hh], tm);
            }
        float rsum[2][2] = {{0.f, 0.f}, {0.f, 0.f}};
#pragma unroll
        for (int mt = 0; mt < 2; mt++)
#pragma unroll
            for (int nt = 0; nt < 4; nt++) {
                float e0 = __expf(sc[mt][nt][0] - mnew[mt][0]);
                float e1 = __expf(sc[mt][nt][1] - mnew[mt][0]);
                float e2 = __expf(sc[mt][nt][2] - mnew[mt][1]);
                float e3 = __expf(sc[mt][nt][3] - mnew[mt][1]);
                rsum[mt][0] += e0 + e1;
                rsum[mt][1] += e2 + e3;
                int r0 = wm * 32 + mt * 16 + g;
                int cl = wn * 32 + nt * 8 + 2 * t;
                *(unsigned*)&smh[OFF_P + r0 * PS_STR + cl]       = h2pack(e0, e1);
                *(unsigned*)&smh[OFF_P + (r0 + 8) * PS_STR + cl] = h2pack(e2, e3);
            }
#pragma unroll
        for (int mt = 0; mt < 2; mt++)
#pragma unroll
            for (int hh = 0; hh < 2; hh++) {
                float v = rsum[mt][hh];
                v += __shfl_xor_sync(0xffffffffu, v, 1);
                v += __shfl_xor_sync(0xffffffffu, v, 2);
                rsum[mt][hh] = v;
            }
        if (t == 0) {
#pragma unroll
            for (int mt = 0; mt < 2; mt++)
#pragma unroll
                for (int hh = 0; hh < 2; hh++)
                    smf[SOFF_RSUM + wn * 128 + wm * 32 + mt * 16 + g + 8 * hh] = rsum[mt][hh];
        }
#pragma unroll
        for (int mt = 0; mt < 2; mt++) {
            float c0 = __expf(mold[mt][0] - mnew[mt][0]);
            float c1 = __expf(mold[mt][1] - mnew[mt][1]);
#pragma unroll
            for (int nt = 0; nt < 8; nt++) {
                accz[mt][nt][0] *= c0; accz[mt][nt][1] *= c0;
                accz[mt][nt][2] *= c1; accz[mt][nt][3] *= c1;
            }
        }
        __syncthreads();

        if (tid < 128) {
            int r = tid;
            float tm = fmaxf(smf[SOFF_RMAX + r], smf[SOFF_RMAX + 128 + r]);
            float mo = smf[SOFF_M + r];
            float mn = fmaxf(mo, tm);
            float corr = __expf(mo - mn);
            smf[SOFF_L + r] = smf[SOFF_L + r] * corr +
                              smf[SOFF_RSUM + r] + smf[SOFF_RSUM + 128 + r];
            smf[SOFF_M + r] = mn;
        }

        {
            unsigned pbase = sptr(smh + OFF_P) +
                ((wm * 32 + (lane & 15)) * PS_STR + (lane >> 4) * 8) * 2;
            unsigned vbase = sptr(smh + OFF_V) +
                ((lane & 15) * VS_STR + wn * 64 + (lane >> 4) * 8) * 2;
#pragma unroll
            for (int ks = 0; ks < 4; ks++) {
                unsigned a0[4], a1[4];
                ldsm4(a0, pbase + ks * 32);
                ldsm4(a1, pbase + 16 * PS_STR * 2 + ks * 32);
                unsigned vf[4][4];
#pragma unroll
                for (int p = 0; p < 4; p++)
                    ldsm4t(vf[p], vbase + ks * 16 * VS_STR * 2 + p * 32);
#pragma unroll
                for (int p = 0; p < 4; p++) {
                    mma16816(accz[0][2 * p],     a0, vf[p][0], vf[p][1]);
                    mma16816(accz[0][2 * p + 1], a0, vf[p][2], vf[p][3]);
                    mma16816(accz[1][2 * p],     a1, vf[p][0], vf[p][1]);
                    mma16816(accz[1][2 * p + 1], a1, vf[p][2], vf[p][3]);
                }
            }
        }
    }

    __syncthreads();
#pragma unroll
    for (int mt = 0; mt < 2; mt++) {
        int r0 = wm * 32 + mt * 16 + g;
        float inv0 = 1.0f / smf[SOFF_L + r0];
        float inv1 = 1.0f / smf[SOFF_L + r0 + 8];
#pragma unroll
        for (int nt = 0; nt < 8; nt++) {
            int col = wn * 64 + nt * 8 + 2 * t;
            __half* d0 = Og + ((size_t)(b * NS + q0 + r0)) * ND + h * NK + col;
            *(unsigned*)(d0)          = h2pack(accz[mt][nt][0] * inv0, accz[mt][nt][1] * inv0);
            *(unsigned*)(d0 + 8 * ND) = h2pack(accz[mt][nt][2] * inv1, accz[mt][nt][3] * inv1);
        }
    }
}

// ---------------- fused residual add + LayerNorm -----------------------------
__global__ __launch_bounds__(256) void add_ln_kernel(
    const float* __restrict__ X, const float* __restrict__ R,
    const float* __restrict__ ga, const float* __restrict__ be,
    float* __restrict__ O, __half* __restrict__ O16)
{
    __shared__ float red1[8];
    __shared__ float red2[8];
    __shared__ float s_mean, s_rstd;
    const int row = blockIdx.x;
    const int tid = threadIdx.x;
    const size_t base = (size_t)row * ND;

    float4 a = *(const float4*)(X + base + tid * 4);
    float4 r = *(const float4*)(R + base + tid * 4);
    float v0 = a.x + r.x, v1 = a.y + r.y, v2 = a.z + r.z, v3 = a.w + r.w;

    float s = v0 + v1 + v2 + v3;
#pragma unroll
    for (int o = 16; o > 0; o >>= 1) s += __shfl_xor_sync(0xffffffffu, s, o);
    if ((tid & 31) == 0) red1[tid >> 5] = s;
    __syncthreads();
    if (tid == 0) {
        float tt = 0.f;
#pragma unroll
        for (int i = 0; i < 8; i++) tt += red1[i];
        s_mean = tt * (1.0f / ND);
    }
    __syncthreads();
    const float mean = s_mean;
    float d0 = v0 - mean, d1 = v1 - mean, d2 = v2 - mean, d3 = v3 - mean;
    float q = d0 * d0 + d1 * d1 + d2 * d2 + d3 * d3;
#pragma unroll
    for (int o = 16; o > 0; o >>= 1) q += __shfl_xor_sync(0xffffffffu, q, o);
    if ((tid & 31) == 0) red2[tid >> 5] = q;
    __syncthreads();
    if (tid == 0) {
        float tt = 0.f;
#pragma unroll
        for (int i = 0; i < 8; i++) tt += red2[i];
        s_rstd = rsqrtf(tt * (1.0f / ND) + 1e-5f);
    }
    __syncthreads();
    const float rstd = s_rstd;

    float4 g4 = *(const float4*)(ga + tid * 4);
    float4 b4 = *(const float4*)(be + tid * 4);
    float4 o4;
    o4.x = d0 * rstd * g4.x + b4.x;
    o4.y = d1 * rstd * g4.y + b4.y;
    o4.z = d2 * rstd * g4.z + b4.z;
    o4.w = d3 * rstd * g4.w + b4.w;
    *(float4*)(O + base + tid * 4) = o4;
    uint2 hh; hh.x = h2pack(o4.x, o4.y); hh.y = h2pack(o4.z, o4.w);
    *(uint2*)(O16 + base + tid * 4) = hh;
}

// ---------------- launcher ---------------------------------------------------
extern "C" void kernel_launch(void* const* d_in, const int* in_sizes, int n_in,
                              void* d_out, int out_size) {
    (void)in_sizes; (void)n_in; (void)out_size;
    const float* x    = (const float*)d_in[0];
    const int*   mask = (const int*)  d_in[1];
    const float* wq   = (const float*)d_in[2];
    const float* bq   = (const float*)d_in[3];
    const float* wk   = (const float*)d_in[4];
    const float* bk   = (const float*)d_in[5];
    const float* wv   = (const float*)d_in[6];
    const float* bv   = (const float*)d_in[7];
    const float* wo   = (const float*)d_in[8];
    const float* bo   = (const float*)d_in[9];
    const float* w1   = (const float*)d_in[10];
    const float* b1   = (const float*)d_in[11];
    const float* w2   = (const float*)d_in[12];
    const float* b2   = (const float*)d_in[13];
    const float* l1g  = (const float*)d_in[14];
    const float* l1b  = (const float*)d_in[15];
    const float* l2g  = (const float*)d_in[16];
    const float* l2b  = (const float*)d_in[17];

    float *px, *pt1;
    __half *px16, *pq, *pk, *pv, *pao, *ph, *pwtd, *pwtq;
    cudaGetSymbolAddress((void**)&px,   g_x);
    cudaGetSymbolAddress((void**)&pt1,  g_t1);
    cudaGetSymbolAddress((void**)&px16, g_x16);
    cudaGetSymbolAddress((void**)&pq,   g_q);
    cudaGetSymbolAddress((void**)&pk,   g_k);
    cudaGetSymbolAddress((void**)&pv,   g_v);
    cudaGetSymbolAddress((void**)&pao,  g_ao);
    cudaGetSymbolAddress((void**)&ph,   g_h);
    cudaGetSymbolAddress((void**)&pwtd, g_wtd);
    cudaGetSymbolAddress((void**)&pwtq, g_wtq);

    cudaFuncSetAttribute(gemm_v2, cudaFuncAttributeMaxDynamicSharedMemorySize, GEMM_SMEM_BYTES);
    cudaFuncSetAttribute(attn_f16, cudaFuncAttributeMaxDynamicSharedMemorySize, ATTN_SMEM_BYTES);

    // weight transposes (layer-invariant)
    tr_dense<<<dim3(32, 32, 12), dim3(32, 8)>>>(wo, w1, w2, pwtd);
    tr_qkv  <<<dim3(4,  32, 96), dim3(32, 8)>>>(wq, wk, wv, pwtq);

    copy_in<<<(NM * ND / 4) / 256, 256>>>((const float4*)x, (float4*)px, (uint2*)px16);

    const dim3 ggrid(ND / 128, NM / 128);   // (8, 64)

    for (int l = 0; l < NL; l++) {
        const size_t vof = (size_t)l * ND;

        __half* qkvout[3] = { pq, pk, pv };
        const float* qkvb[3] = { bq + (size_t)l * NH * NK,
                                 bk + (size_t)l * NH * NK,
                                 bv + (size_t)l * NH * NK };
        for (int sel = 0; sel < 3; sel++) {
            gemm_v2<<<ggrid, 128, GEMM_SMEM_BYTES>>>(
                px16, pwtq + (size_t)(l * 3 + sel) * ND * ND,
                qkvb[sel], (float*)0, qkvout[sel], 2);
        }

        attn_f16<<<dim3(NS / 128, NB * NH), 256, ATTN_SMEM_BYTES>>>(
            pq, pk, pv, mask, pao);

        gemm_v2<<<ggrid, 128, GEMM_SMEM_BYTES>>>(
            pao, pwtd + (size_t)(l * 3 + 0) * ND * ND, bo + vof, pt1, (__half*)0, 0);
        add_ln_kernel<<<NM, 256>>>(px, pt1, l1g + vof, l1b + vof, px, px16);

        gemm_v2<<<ggrid, 128, GEMM_SMEM_BYTES>>>(
            px16, pwtd + (size_t)(l * 3 + 1) * ND * ND, b1 + vof, (float*)0, ph, 1);
        gemm_v2<<<ggrid, 128, GEMM_SMEM_BYTES>>>(
            ph, pwtd + (size_t)(l * 3 + 2) * ND * ND, b2 + vof, pt1, (__half*)0, 0);

        float* dst = (l == NL - 1) ? (float*)d_out : px;
        add_ln_kernel<<<NM, 256>>>(px, pt1, l2g + vof, l2b + vof, dst, px16);
    }
}